// round 1
// baseline (speedup 1.0000x reference)
#include <cuda_runtime.h>

// ---------------------------------------------------------------------------
// 3-layer GAT (chess NodeEncoder). Fixed sizes from the reference.
// ---------------------------------------------------------------------------
constexpr int N    = 32768;
constexpr int EPER = 16384;
constexpr int T    = 8;
constexpr int E0   = T * EPER;   // 131072 typed edges
constexpr int E    = E0 + N;     // + self loops = 163840
constexpr int H    = 4;
constexpr float NEG = 0.2f;

// ---------------------------- scratch (device globals) ---------------------
__device__ float g_hp[(size_t)N * 2048];   // per-layer projected features [N, H*dout], max layer3
__device__ float g_hbuf[(size_t)N * 128];  // inter-layer activations (max width 128)
__device__ float g_ssrc[N * H];
__device__ float g_sdst[N * H];
__device__ float g_w[E * H];               // edge attention weights
__device__ float g_etab[(T + 1) * H];      // per-(edge-type, head) score table
__device__ int   g_src[E], g_dst[E], g_et[E];
__device__ int   g_deg[N], g_rowptr[N + 1], g_fill[N], g_eperm[E];

// ---------------------------- graph build (CSR by dst) ---------------------
__global__ void k_zero_deg() {
    int i = blockIdx.x * blockDim.x + threadIdx.x;
    if (i < N) g_deg[i] = 0;
}

__global__ void k_build(const int* __restrict__ eit) {
    int e = blockIdx.x * blockDim.x + threadIdx.x;
    if (e >= E) return;
    int s, d, t;
    if (e < E0) {
        t = e / EPER;
        int i = e - t * EPER;
        s = eit[t * 2 * EPER + i];
        d = eit[t * 2 * EPER + EPER + i];
    } else {
        s = d = e - E0;
        t = T;          // self-loop pseudo-type (mean one-hot)
    }
    g_src[e] = s; g_dst[e] = d; g_et[e] = t;
    atomicAdd(&g_deg[d], 1);
}

// single-block exclusive scan of g_deg (N = 1024 * 32 exactly)
__global__ void k_scan() {
    __shared__ int sh[1024];
    int t = threadIdx.x;
    int base = t * 32;
    int loc[32];
    int sum = 0;
#pragma unroll
    for (int i = 0; i < 32; i++) { loc[i] = sum; sum += g_deg[base + i]; }
    sh[t] = sum;
    __syncthreads();
    for (int off = 1; off < 1024; off <<= 1) {
        int v = (t >= off) ? sh[t - off] : 0;
        __syncthreads();
        if (t >= off) sh[t] += v;
        __syncthreads();
    }
    int prev = (t == 0) ? 0 : sh[t - 1];
#pragma unroll
    for (int i = 0; i < 32; i++) {
        int v = prev + loc[i];
        g_rowptr[base + i] = v;
        g_fill[base + i]   = v;
    }
    if (t == 1023) g_rowptr[N] = sh[1023];
}

__global__ void k_scatter() {
    int e = blockIdx.x * blockDim.x + threadIdx.x;
    if (e >= E) return;
    int pos = atomicAdd(&g_fill[g_dst[e]], 1);
    g_eperm[pos] = e;
}

// ---------------------------- GEMM: C[M,NN] = A[M,K] @ B[K,NN] -------------
// 128x128 block tile, BK=8, 256 threads, 8x8 per thread. K, NN multiples of 8/128.
__global__ void k_gemm(const float* __restrict__ A, const float* __restrict__ B,
                       float* __restrict__ C, int M, int K, int NN) {
    __shared__ float As[8][128];
    __shared__ float Bs[8][128];
    int tid = threadIdx.x;
    int bm = blockIdx.y * 128, bn = blockIdx.x * 128;
    int ty = tid >> 4, tx = tid & 15;
    float acc[8][8];
#pragma unroll
    for (int i = 0; i < 8; i++)
#pragma unroll
        for (int j = 0; j < 8; j++) acc[i][j] = 0.f;

    for (int k0 = 0; k0 < K; k0 += 8) {
#pragma unroll
        for (int i = 0; i < 4; i++) {
            int p = tid * 4 + i;
            int m = p >> 3, kk = p & 7;
            As[kk][m] = A[(size_t)(bm + m) * K + k0 + kk];
        }
        {
            int k = tid >> 5, n = (tid & 31) * 4;
            float4 v = *reinterpret_cast<const float4*>(&B[(size_t)(k0 + k) * NN + bn + n]);
            *reinterpret_cast<float4*>(&Bs[k][n]) = v;
        }
        __syncthreads();
#pragma unroll
        for (int kk = 0; kk < 8; kk++) {
            float a[8], b[8];
#pragma unroll
            for (int i = 0; i < 8; i++) a[i] = As[kk][ty * 8 + i];
#pragma unroll
            for (int j = 0; j < 8; j++) b[j] = Bs[kk][tx * 8 + j];
#pragma unroll
            for (int i = 0; i < 8; i++)
#pragma unroll
                for (int j = 0; j < 8; j++) acc[i][j] += a[i] * b[j];
        }
        __syncthreads();
    }
#pragma unroll
    for (int i = 0; i < 8; i++) {
        size_t row = (size_t)(bm + ty * 8 + i) * NN + bn + tx * 8;
#pragma unroll
        for (int j = 0; j < 8; j++) C[row + j] = acc[i][j];
    }
}

// ---------------------------- per-node attention scores --------------------
// one warp per (node, head): s_src[n,h] = hp[n,h,:]·asrc[h,:], same for dst
__global__ void k_scores(const float* __restrict__ hp, const float* __restrict__ asrc,
                         const float* __restrict__ adst, int dout) {
    int gw = (blockIdx.x * blockDim.x + threadIdx.x) >> 5;
    int lane = threadIdx.x & 31;
    if (gw >= N * H) return;
    int n = gw >> 2, h = gw & 3;
    int HC = H * dout;
    const float* row = hp + (size_t)n * HC + h * dout;
    const float* as = asrc + h * dout;
    const float* ad = adst + h * dout;
    float vs = 0.f, vd = 0.f;
    for (int c = lane; c < dout; c += 32) {
        float x = row[c];
        vs += x * as[c];
        vd += x * ad[c];
    }
#pragma unroll
    for (int o = 16; o > 0; o >>= 1) {
        vs += __shfl_xor_sync(0xffffffffu, vs, o);
        vd += __shfl_xor_sync(0xffffffffu, vd, o);
    }
    if (lane == 0) { g_ssrc[gw] = vs; g_sdst[gw] = vd; }
}

// per-(edge-type, head) score table; slot T = self-loop (mean one-hot)
__global__ void k_edgetable(const float* __restrict__ We, const float* __restrict__ ae,
                            int dout) {
    __shared__ float sh[T][H];
    int tid = threadIdx.x;
    int HC = H * dout;
    if (tid < T * H) {
        int t = tid >> 2, h = tid & 3;
        float s = 0.f;
        for (int c = 0; c < dout; c++) s += We[t * HC + h * dout + c] * ae[h * dout + c];
        sh[t][h] = s;
        g_etab[t * H + h] = s;
    }
    __syncthreads();
    if (tid < H) {
        float s = 0.f;
        for (int t = 0; t < T; t++) s += sh[t][tid];
        g_etab[T * H + tid] = s * (1.0f / T);
    }
}

// ---------------------------- segment softmax over dst ---------------------
__global__ void k_softmax() {
    int idx = blockIdx.x * blockDim.x + threadIdx.x;
    if (idx >= N * H) return;
    int n = idx >> 2, h = idx & 3;
    int b0 = g_rowptr[n], b1 = g_rowptr[n + 1];
    float sd = g_sdst[idx];
    float mx = -1e30f;
    for (int j = b0; j < b1; j++) {
        int e = g_eperm[j];
        float a = g_ssrc[g_src[e] * H + h] + sd + g_etab[g_et[e] * H + h];
        a = (a > 0.f) ? a : NEG * a;
        g_w[e * H + h] = a;
        mx = fmaxf(mx, a);
    }
    float s = 0.f;
    for (int j = b0; j < b1; j++) {
        int e = g_eperm[j];
        float ex = expf(g_w[e * H + h] - mx);
        g_w[e * H + h] = ex;
        s += ex;
    }
    float inv = 1.f / s;
    for (int j = b0; j < b1; j++) {
        int e = g_eperm[j];
        g_w[e * H + h] *= inv;
    }
}

// ---------------------------- weighted aggregation + head mean + bias ------
// block per dst node; thread owns channels c = tid + i*NT across all 4 heads
template <int DOUT, int NT, bool RELU>
__global__ void k_aggregate(const float* __restrict__ hp, const float* __restrict__ bias,
                            float* __restrict__ out) {
    constexpr int NC = DOUT / NT;
    int n = blockIdx.x;
    int tid = threadIdx.x;
    int b0 = g_rowptr[n], b1 = g_rowptr[n + 1];
    float acc[NC][H];
#pragma unroll
    for (int i = 0; i < NC; i++)
#pragma unroll
        for (int h = 0; h < H; h++) acc[i][h] = 0.f;

    for (int j = b0; j < b1; j++) {
        int e = g_eperm[j];
        const float* row = hp + (size_t)g_src[e] * (H * DOUT);
        float w[H];
#pragma unroll
        for (int h = 0; h < H; h++) w[h] = g_w[e * H + h];
#pragma unroll
        for (int i = 0; i < NC; i++) {
            int c = tid + i * NT;
#pragma unroll
            for (int h = 0; h < H; h++) acc[i][h] += row[h * DOUT + c] * w[h];
        }
    }
#pragma unroll
    for (int i = 0; i < NC; i++) {
        int c = tid + i * NT;
        float v = (acc[i][0] + acc[i][1] + acc[i][2] + acc[i][3]) * 0.25f + bias[c];
        if (RELU) v = fmaxf(v, 0.f);
        out[(size_t)n * DOUT + c] = v;
    }
}

// ---------------------------------------------------------------------------
extern "C" void kernel_launch(void* const* d_in, const int* in_sizes, int n_in,
                              void* d_out, int out_size) {
    const float* x   = (const float*)d_in[0];
    const int*   eit = (const int*)d_in[1];
    const float* W1  = (const float*)d_in[2];
    const float* We1 = (const float*)d_in[3];
    const float* as1 = (const float*)d_in[4];
    const float* ad1 = (const float*)d_in[5];
    const float* ae1 = (const float*)d_in[6];
    const float* b1  = (const float*)d_in[7];
    const float* W2  = (const float*)d_in[8];
    const float* We2 = (const float*)d_in[9];
    const float* as2 = (const float*)d_in[10];
    const float* ad2 = (const float*)d_in[11];
    const float* ae2 = (const float*)d_in[12];
    const float* b2  = (const float*)d_in[13];
    const float* W3  = (const float*)d_in[14];
    const float* We3 = (const float*)d_in[15];
    const float* as3 = (const float*)d_in[16];
    const float* ad3 = (const float*)d_in[17];
    const float* ae3 = (const float*)d_in[18];
    const float* b3  = (const float*)d_in[19];
    float* out = (float*)d_out;

    float *hp = nullptr, *hbuf = nullptr;
    cudaGetSymbolAddress((void**)&hp, g_hp);
    cudaGetSymbolAddress((void**)&hbuf, g_hbuf);

    // ---- graph build (CSR by dst) ----
    k_zero_deg<<<N / 256, 256>>>();
    k_build<<<E / 256, 256>>>(eit);
    k_scan<<<1, 1024>>>();
    k_scatter<<<E / 256, 256>>>();

    // ---- layer 1: 16 -> 32 ----
    k_gemm<<<dim3(1, N / 128), 256>>>(x, W1, hp, N, 16, 128);
    k_scores<<<(N * H) / 8, 256>>>(hp, as1, ad1, 32);
    k_edgetable<<<1, 64>>>(We1, ae1, 32);
    k_softmax<<<(N * H) / 256, 256>>>();
    k_aggregate<32, 32, true><<<N, 32>>>(hp, b1, hbuf);

    // ---- layer 2: 32 -> 128 ----
    k_gemm<<<dim3(4, N / 128), 256>>>(hbuf, W2, hp, N, 32, 512);
    k_scores<<<(N * H) / 8, 256>>>(hp, as2, ad2, 128);
    k_edgetable<<<1, 64>>>(We2, ae2, 128);
    k_softmax<<<(N * H) / 256, 256>>>();
    k_aggregate<128, 128, true><<<N, 128>>>(hp, b2, hbuf);

    // ---- layer 3: 128 -> 512 (no relu, write d_out) ----
    k_gemm<<<dim3(16, N / 128), 256>>>(hbuf, W3, hp, N, 128, 2048);
    k_scores<<<(N * H) / 8, 256>>>(hp, as3, ad3, 512);
    k_edgetable<<<1, 64>>>(We3, ae3, 512);
    k_softmax<<<(N * H) / 256, 256>>>();
    k_aggregate<512, 128, false><<<N, 128>>>(hp, b3, out);
}

// round 2
// speedup vs baseline: 1.5568x; 1.5568x over previous
#include <cuda_runtime.h>

constexpr int N    = 32768;
constexpr int EPER = 16384;
constexpr int T    = 8;
constexpr int E0   = T * EPER;   // 131072 typed edges
constexpr int E    = E0 + N;     // + self loops = 163840
constexpr int H    = 4;
constexpr float NEG = 0.2f;

// ---------------------------- scratch (device globals) ---------------------
__device__ float g_agg[(size_t)N * 512];    // input-space aggregation [N, H*K], max H*128
__device__ float g_hbuf[(size_t)N * 128];   // inter-layer activations (max width 128)
__device__ float g_ssrc[N * H];
__device__ float g_sdst[N * H];
__device__ float g_w[E * H];                // edge attention weights
__device__ float g_etab[(T + 1) * H];       // per-(edge-type, head) score table
__device__ float g_usrc[H * 128];           // W_h @ asrc_h  (per-head, K wide)
__device__ float g_udst[H * 128];
__device__ float g_wstack[512 * 512];       // [H*K, dout] head-blocked W / H
__device__ int   g_src[E], g_dst[E], g_et[E];
__device__ int   g_deg[N], g_rowptr[N + 1], g_fill[N], g_eperm[E];

// ---------------------------- graph build (CSR by dst) ---------------------
__global__ void k_zero_deg() {
    int i = blockIdx.x * blockDim.x + threadIdx.x;
    if (i < N) g_deg[i] = 0;
}

__global__ void k_build(const int* __restrict__ eit) {
    int e = blockIdx.x * blockDim.x + threadIdx.x;
    if (e >= E) return;
    int s, d, t;
    if (e < E0) {
        t = e / EPER;
        int i = e - t * EPER;
        s = eit[t * 2 * EPER + i];
        d = eit[t * 2 * EPER + EPER + i];
    } else {
        s = d = e - E0;
        t = T;
    }
    g_src[e] = s; g_dst[e] = d; g_et[e] = t;
    atomicAdd(&g_deg[d], 1);
}

__global__ void k_scan() {
    __shared__ int sh[1024];
    int t = threadIdx.x;
    int base = t * 32;
    int loc[32];
    int sum = 0;
#pragma unroll
    for (int i = 0; i < 32; i++) { loc[i] = sum; sum += g_deg[base + i]; }
    sh[t] = sum;
    __syncthreads();
    for (int off = 1; off < 1024; off <<= 1) {
        int v = (t >= off) ? sh[t - off] : 0;
        __syncthreads();
        if (t >= off) sh[t] += v;
        __syncthreads();
    }
    int prev = (t == 0) ? 0 : sh[t - 1];
#pragma unroll
    for (int i = 0; i < 32; i++) {
        int v = prev + loc[i];
        g_rowptr[base + i] = v;
        g_fill[base + i]   = v;
    }
    if (t == 1023) g_rowptr[N] = sh[1023];
}

__global__ void k_scatter() {
    int e = blockIdx.x * blockDim.x + threadIdx.x;
    if (e >= E) return;
    int pos = atomicAdd(&g_fill[g_dst[e]], 1);
    g_eperm[pos] = e;
}

// ------------- per-layer prep: U vectors, edge-type table, Wstack ----------
// Usrc[h*K+k] = sum_d W[k, h*dout+d] * asrc[h,d]   (same for dst)
__global__ void k_prep_u(const float* __restrict__ W, const float* __restrict__ asrc,
                         const float* __restrict__ adst, int K, int dout) {
    int idx = blockIdx.x * blockDim.x + threadIdx.x;
    if (idx >= H * K) return;
    int h = idx / K, k = idx % K;
    const float* wr = W + (size_t)k * (H * dout) + h * dout;
    const float* as = asrc + h * dout;
    const float* ad = adst + h * dout;
    float vs = 0.f, vd = 0.f;
    for (int d = 0; d < dout; d++) { vs += wr[d] * as[d]; vd += wr[d] * ad[d]; }
    g_usrc[idx] = vs;
    g_udst[idx] = vd;
}

__global__ void k_edgetable(const float* __restrict__ We, const float* __restrict__ ae,
                            int dout) {
    __shared__ float sh[T][H];
    int tid = threadIdx.x;
    int HC = H * dout;
    if (tid < T * H) {
        int t = tid >> 2, h = tid & 3;
        float s = 0.f;
        for (int c = 0; c < dout; c++) s += We[t * HC + h * dout + c] * ae[h * dout + c];
        sh[t][h] = s;
        g_etab[t * H + h] = s;
    }
    __syncthreads();
    if (tid < H) {
        float s = 0.f;
        for (int t = 0; t < T; t++) s += sh[t][tid];
        g_etab[T * H + tid] = s * (1.0f / T);
    }
}

// Wstack[(h*K+k), d] = W[k, h*dout+d] / H
__global__ void k_wstack(const float* __restrict__ W, int K, int dout) {
    int idx = blockIdx.x * blockDim.x + threadIdx.x;
    if (idx >= H * K * dout) return;
    int d = idx % dout;
    int hk = idx / dout;
    int h = hk / K, k = hk % K;
    g_wstack[idx] = W[(size_t)k * (H * dout) + h * dout + d] * 0.25f;
}

// ---------------------------- per-node attention scores --------------------
// warp per node: s_src[n,h] = h[n,:] . Usrc[h,:]
__global__ void k_scores(const float* __restrict__ h, int K) {
    int gw = (blockIdx.x * blockDim.x + threadIdx.x) >> 5;
    int lane = threadIdx.x & 31;
    if (gw >= N) return;
    const float* row = h + (size_t)gw * K;
    float acc[2][H];
#pragma unroll
    for (int i = 0; i < 2; i++)
#pragma unroll
        for (int hh = 0; hh < H; hh++) acc[i][hh] = 0.f;
    for (int k = lane; k < K; k += 32) {
        float x = row[k];
#pragma unroll
        for (int hh = 0; hh < H; hh++) {
            acc[0][hh] += x * g_usrc[hh * K + k];
            acc[1][hh] += x * g_udst[hh * K + k];
        }
    }
#pragma unroll
    for (int i = 0; i < 2; i++)
#pragma unroll
        for (int hh = 0; hh < H; hh++)
#pragma unroll
            for (int o = 16; o > 0; o >>= 1)
                acc[i][hh] += __shfl_xor_sync(0xffffffffu, acc[i][hh], o);
    if (lane < H)      g_ssrc[gw * H + lane] = acc[0][lane];
    else if (lane < 2 * H) g_sdst[gw * H + (lane - H)] = acc[1][lane - H];
}

// ---------------------------- segment softmax over dst ---------------------
__global__ void k_softmax() {
    int idx = blockIdx.x * blockDim.x + threadIdx.x;
    if (idx >= N * H) return;
    int n = idx >> 2, h = idx & 3;
    int b0 = g_rowptr[n], b1 = g_rowptr[n + 1];
    float sd = g_sdst[idx];
    float mx = -1e30f;
    for (int j = b0; j < b1; j++) {
        int e = g_eperm[j];
        float a = g_ssrc[g_src[e] * H + h] + sd + g_etab[g_et[e] * H + h];
        a = (a > 0.f) ? a : NEG * a;
        g_w[e * H + h] = a;
        mx = fmaxf(mx, a);
    }
    float s = 0.f;
    for (int j = b0; j < b1; j++) {
        int e = g_eperm[j];
        float ex = expf(g_w[e * H + h] - mx);
        g_w[e * H + h] = ex;
        s += ex;
    }
    float inv = 1.f / s;
    for (int j = b0; j < b1; j++) {
        int e = g_eperm[j];
        g_w[e * H + h] *= inv;
    }
}

// ---------------- input-space aggregation: agg[n, h*K+k] -------------------
// block = 128 threads = (128/K) nodes; per edge read h_src[k] once, 4 head accs
template <int K>
__global__ void k_aggregate_in(const float* __restrict__ h, float* __restrict__ agg) {
    constexpr int NPB = 128 / K;
    int tid = threadIdx.x;
    int n = blockIdx.x * NPB + tid / K;
    int k = tid % K;
    int b0 = g_rowptr[n], b1 = g_rowptr[n + 1];
    float a0 = 0.f, a1 = 0.f, a2 = 0.f, a3 = 0.f;
    for (int j = b0; j < b1; j++) {
        int e = g_eperm[j];
        float v = h[(size_t)g_src[e] * K + k];
        const float* w = &g_w[e * H];
        a0 += w[0] * v; a1 += w[1] * v; a2 += w[2] * v; a3 += w[3] * v;
    }
    size_t base = (size_t)n * (H * K) + k;
    agg[base]         = a0;
    agg[base + K]     = a1;
    agg[base + 2 * K] = a2;
    agg[base + 3 * K] = a3;
}

// ------------- small GEMM (dout<=32): C = A[N,K] @ B[K,NN] + bias ----------
__global__ void k_gemm_small(const float* __restrict__ A, const float* __restrict__ B,
                             const float* __restrict__ bias, float* __restrict__ C,
                             int K, int NN, int relu) {
    int idx = blockIdx.x * blockDim.x + threadIdx.x;
    int n = idx / NN, d = idx % NN;
    if (n >= N) return;
    const float* ar = A + (size_t)n * K;
    float acc = 0.f;
    for (int k = 0; k < K; k++) acc += ar[k] * B[k * NN + d];
    acc += bias[d];
    if (relu) acc = fmaxf(acc, 0.f);
    C[(size_t)n * NN + d] = acc;
}

// ------------- tiled GEMM 128x128, BK=16, fused bias(+relu) ----------------
__global__ void k_gemm(const float* __restrict__ A, const float* __restrict__ B,
                       const float* __restrict__ bias, float* __restrict__ C,
                       int K, int NN, int relu) {
    __shared__ float As[16][128];
    __shared__ float Bs[16][128];
    int tid = threadIdx.x;
    int bm = blockIdx.y * 128, bn = blockIdx.x * 128;
    int ty = tid >> 4, tx = tid & 15;
    float acc[8][8];
#pragma unroll
    for (int i = 0; i < 8; i++)
#pragma unroll
        for (int j = 0; j < 8; j++) acc[i][j] = 0.f;

    for (int k0 = 0; k0 < K; k0 += 16) {
#pragma unroll
        for (int i = 0; i < 2; i++) {
            int f = tid * 2 + i;                  // 512 float4 tiles of A
            int m = f >> 2, kq = f & 3;
            float4 v = *reinterpret_cast<const float4*>(&A[(size_t)(bm + m) * K + k0 + kq * 4]);
            As[kq * 4 + 0][m] = v.x;
            As[kq * 4 + 1][m] = v.y;
            As[kq * 4 + 2][m] = v.z;
            As[kq * 4 + 3][m] = v.w;
        }
#pragma unroll
        for (int i = 0; i < 2; i++) {
            int f = tid * 2 + i;                  // 512 float4 tiles of B
            int k = f >> 5, n4 = f & 31;
            float4 v = *reinterpret_cast<const float4*>(&B[(size_t)(k0 + k) * NN + bn + n4 * 4]);
            *reinterpret_cast<float4*>(&Bs[k][n4 * 4]) = v;
        }
        __syncthreads();
#pragma unroll
        for (int kk = 0; kk < 16; kk++) {
            float a[8], b[8];
            *reinterpret_cast<float4*>(&a[0]) = *reinterpret_cast<const float4*>(&As[kk][ty * 8]);
            *reinterpret_cast<float4*>(&a[4]) = *reinterpret_cast<const float4*>(&As[kk][ty * 8 + 4]);
            *reinterpret_cast<float4*>(&b[0]) = *reinterpret_cast<const float4*>(&Bs[kk][tx * 8]);
            *reinterpret_cast<float4*>(&b[4]) = *reinterpret_cast<const float4*>(&Bs[kk][tx * 8 + 4]);
#pragma unroll
            for (int i = 0; i < 8; i++)
#pragma unroll
                for (int j = 0; j < 8; j++) acc[i][j] += a[i] * b[j];
        }
        __syncthreads();
    }
#pragma unroll
    for (int i = 0; i < 8; i++) {
        size_t row = (size_t)(bm + ty * 8 + i) * NN + bn + tx * 8;
#pragma unroll
        for (int j = 0; j < 8; j++) {
            float v = acc[i][j] + bias[bn + tx * 8 + j];
            if (relu) v = fmaxf(v, 0.f);
            C[row + j] = v;
        }
    }
}

// ---------------------------------------------------------------------------
extern "C" void kernel_launch(void* const* d_in, const int* in_sizes, int n_in,
                              void* d_out, int out_size) {
    const float* x   = (const float*)d_in[0];
    const int*   eit = (const int*)d_in[1];
    const float* W1  = (const float*)d_in[2];
    const float* We1 = (const float*)d_in[3];
    const float* as1 = (const float*)d_in[4];
    const float* ad1 = (const float*)d_in[5];
    const float* ae1 = (const float*)d_in[6];
    const float* b1  = (const float*)d_in[7];
    const float* W2  = (const float*)d_in[8];
    const float* We2 = (const float*)d_in[9];
    const float* as2 = (const float*)d_in[10];
    const float* ad2 = (const float*)d_in[11];
    const float* ae2 = (const float*)d_in[12];
    const float* b2  = (const float*)d_in[13];
    const float* W3  = (const float*)d_in[14];
    const float* We3 = (const float*)d_in[15];
    const float* as3 = (const float*)d_in[16];
    const float* ad3 = (const float*)d_in[17];
    const float* ae3 = (const float*)d_in[18];
    const float* b3  = (const float*)d_in[19];
    float* out = (float*)d_out;

    float *agg = nullptr, *hbuf = nullptr, *wst = nullptr;
    cudaGetSymbolAddress((void**)&agg, g_agg);
    cudaGetSymbolAddress((void**)&hbuf, g_hbuf);
    cudaGetSymbolAddress((void**)&wst, g_wstack);

    // ---- graph build (CSR by dst) ----
    k_zero_deg<<<N / 256, 256>>>();
    k_build<<<E / 256, 256>>>(eit);
    k_scan<<<1, 1024>>>();
    k_scatter<<<E / 256, 256>>>();

    // ---- layer 1: K=16 -> dout=32 ----
    k_prep_u<<<1, H * 16>>>(W1, as1, ad1, 16, 32);
    k_edgetable<<<1, 64>>>(We1, ae1, 32);
    k_wstack<<<(H * 16 * 32 + 255) / 256, 256>>>(W1, 16, 32);
    k_scores<<<N / 8, 256>>>(x, 16);
    k_softmax<<<(N * H) / 256, 256>>>();
    k_aggregate_in<16><<<N / 8, 128>>>(x, agg);
    k_gemm_small<<<(N * 32) / 256, 256>>>(agg, wst, b1, hbuf, H * 16, 32, 1);

    // ---- layer 2: K=32 -> dout=128 ----
    k_prep_u<<<1, H * 32>>>(W2, as2, ad2, 32, 128);
    k_edgetable<<<1, 64>>>(We2, ae2, 128);
    k_wstack<<<(H * 32 * 128 + 255) / 256, 256>>>(W2, 32, 128);
    k_scores<<<N / 8, 256>>>(hbuf, 32);
    k_softmax<<<(N * H) / 256, 256>>>();
    k_aggregate_in<32><<<N / 4, 128>>>(hbuf, agg);
    k_gemm<<<dim3(1, N / 128), 256>>>(agg, wst, b2, hbuf, H * 32, 128, 1);

    // ---- layer 3: K=128 -> dout=512 (no relu, writes d_out) ----
    k_prep_u<<<2, 256>>>(W3, as3, ad3, 128, 512);
    k_edgetable<<<1, 64>>>(We3, ae3, 512);
    k_wstack<<<(H * 128 * 512 + 255) / 256, 256>>>(W3, 128, 512);
    k_scores<<<N / 8, 256>>>(hbuf, 128);
    k_softmax<<<(N * H) / 256, 256>>>();
    k_aggregate_in<128><<<N, 128>>>(hbuf, agg);
    k_gemm<<<dim3(4, N / 128), 256>>>(agg, wst, b3, out, H * 128, 512, 0);
}

// round 3
// speedup vs baseline: 2.3423x; 1.5046x over previous
#include <cuda_runtime.h>

constexpr int N    = 32768;
constexpr int EPER = 16384;
constexpr int T    = 8;
constexpr int E0   = T * EPER;   // 131072 typed edges
constexpr int E    = E0 + N;     // + self loops = 163840
constexpr int H    = 4;
constexpr float NEG = 0.2f;

// ---------------------------- scratch (device globals) ---------------------
__device__ float g_agg[(size_t)N * 512];    // input-space aggregation [N, H*K]
__device__ float g_hbuf[(size_t)N * 128];   // inter-layer activations
__device__ float g_ssrc[N * H];
__device__ float g_sdst[N * H];
__device__ float g_w[E * H];                // edge attention weights
__device__ float g_etab[(T + 1) * H];
__device__ float g_usrc[H * 128];
__device__ float g_udst[H * 128];
__device__ float g_wstack[512 * 512];       // [H*K, dout] head-blocked W / H
__device__ int   g_src[E], g_dst[E], g_et[E];
__device__ int   g_deg[N], g_rowptr[N + 1], g_fill[N], g_eperm[E];

// ---------------------------- graph build (CSR by dst) ---------------------
__global__ void k_zero_deg() {
    int i = blockIdx.x * blockDim.x + threadIdx.x;
    if (i < N) g_deg[i] = 0;
}

__global__ void k_build(const int* __restrict__ eit) {
    int e = blockIdx.x * blockDim.x + threadIdx.x;
    if (e >= E) return;
    int s, d, t;
    if (e < E0) {
        t = e / EPER;
        int i = e - t * EPER;
        s = eit[t * 2 * EPER + i];
        d = eit[t * 2 * EPER + EPER + i];
    } else {
        s = d = e - E0;
        t = T;
    }
    g_src[e] = s; g_dst[e] = d; g_et[e] = t;
    atomicAdd(&g_deg[d], 1);
}

__global__ void k_scan() {
    __shared__ int sh[1024];
    int t = threadIdx.x;
    int base = t * 32;
    int loc[32];
    int sum = 0;
#pragma unroll
    for (int i = 0; i < 32; i++) { loc[i] = sum; sum += g_deg[base + i]; }
    sh[t] = sum;
    __syncthreads();
    for (int off = 1; off < 1024; off <<= 1) {
        int v = (t >= off) ? sh[t - off] : 0;
        __syncthreads();
        if (t >= off) sh[t] += v;
        __syncthreads();
    }
    int prev = (t == 0) ? 0 : sh[t - 1];
#pragma unroll
    for (int i = 0; i < 32; i++) {
        int v = prev + loc[i];
        g_rowptr[base + i] = v;
        g_fill[base + i]   = v;
    }
    if (t == 1023) g_rowptr[N] = sh[1023];
}

__global__ void k_scatter() {
    int e = blockIdx.x * blockDim.x + threadIdx.x;
    if (e >= E) return;
    int pos = atomicAdd(&g_fill[g_dst[e]], 1);
    g_eperm[pos] = e;
}

// ------------- per-layer prep ---------------------------------------------
__global__ void k_prep_u(const float* __restrict__ W, const float* __restrict__ asrc,
                         const float* __restrict__ adst, int K, int dout) {
    int idx = blockIdx.x * blockDim.x + threadIdx.x;
    if (idx >= H * K) return;
    int h = idx / K, k = idx % K;
    const float* wr = W + (size_t)k * (H * dout) + h * dout;
    const float* as = asrc + h * dout;
    const float* ad = adst + h * dout;
    float vs = 0.f, vd = 0.f;
    for (int d = 0; d < dout; d++) { vs += wr[d] * as[d]; vd += wr[d] * ad[d]; }
    g_usrc[idx] = vs;
    g_udst[idx] = vd;
}

__global__ void k_edgetable(const float* __restrict__ We, const float* __restrict__ ae,
                            int dout) {
    __shared__ float sh[T][H];
    int tid = threadIdx.x;
    int HC = H * dout;
    if (tid < T * H) {
        int t = tid >> 2, h = tid & 3;
        float s = 0.f;
        for (int c = 0; c < dout; c++) s += We[t * HC + h * dout + c] * ae[h * dout + c];
        sh[t][h] = s;
        g_etab[t * H + h] = s;
    }
    __syncthreads();
    if (tid < H) {
        float s = 0.f;
        for (int t = 0; t < T; t++) s += sh[t][tid];
        g_etab[T * H + tid] = s * (1.0f / T);
    }
}

__global__ void k_wstack(const float* __restrict__ W, int K, int dout) {
    int idx = blockIdx.x * blockDim.x + threadIdx.x;
    if (idx >= H * K * dout) return;
    int d = idx % dout;
    int hk = idx / dout;
    int h = hk / K, k = hk % K;
    g_wstack[idx] = W[(size_t)k * (H * dout) + h * dout + d] * 0.25f;
}

// ---------------------------- per-node attention scores --------------------
__global__ void k_scores(const float* __restrict__ h, int K) {
    int gw = (blockIdx.x * blockDim.x + threadIdx.x) >> 5;
    int lane = threadIdx.x & 31;
    if (gw >= N) return;
    const float* row = h + (size_t)gw * K;
    float acc[2][H];
#pragma unroll
    for (int i = 0; i < 2; i++)
#pragma unroll
        for (int hh = 0; hh < H; hh++) acc[i][hh] = 0.f;
    for (int k = lane; k < K; k += 32) {
        float x = row[k];
#pragma unroll
        for (int hh = 0; hh < H; hh++) {
            acc[0][hh] += x * g_usrc[hh * K + k];
            acc[1][hh] += x * g_udst[hh * K + k];
        }
    }
#pragma unroll
    for (int i = 0; i < 2; i++)
#pragma unroll
        for (int hh = 0; hh < H; hh++)
#pragma unroll
            for (int o = 16; o > 0; o >>= 1)
                acc[i][hh] += __shfl_xor_sync(0xffffffffu, acc[i][hh], o);
    if (lane < H)      g_ssrc[gw * H + lane] = acc[0][lane];
    else if (lane < 2 * H) g_sdst[gw * H + (lane - H)] = acc[1][lane - H];
}

// ---------------------------- segment softmax over dst ---------------------
__global__ void k_softmax() {
    int idx = blockIdx.x * blockDim.x + threadIdx.x;
    if (idx >= N * H) return;
    int n = idx >> 2, h = idx & 3;
    int b0 = g_rowptr[n], b1 = g_rowptr[n + 1];
    float sd = g_sdst[idx];
    float mx = -1e30f;
    for (int j = b0; j < b1; j++) {
        int e = g_eperm[j];
        float a = g_ssrc[g_src[e] * H + h] + sd + g_etab[g_et[e] * H + h];
        a = (a > 0.f) ? a : NEG * a;
        g_w[e * H + h] = a;
        mx = fmaxf(mx, a);
    }
    float s = 0.f;
    for (int j = b0; j < b1; j++) {
        int e = g_eperm[j];
        float ex = expf(g_w[e * H + h] - mx);
        g_w[e * H + h] = ex;
        s += ex;
    }
    float inv = 1.f / s;
    for (int j = b0; j < b1; j++) {
        int e = g_eperm[j];
        g_w[e * H + h] *= inv;
    }
}

// ---------------- input-space aggregation: agg[n, h*K+k] -------------------
template <int K>
__global__ void k_aggregate_in(const float* __restrict__ h, float* __restrict__ agg) {
    constexpr int NPB = 128 / K;
    int tid = threadIdx.x;
    int n = blockIdx.x * NPB + tid / K;
    int k = tid % K;
    int b0 = g_rowptr[n], b1 = g_rowptr[n + 1];
    float a0 = 0.f, a1 = 0.f, a2 = 0.f, a3 = 0.f;
    for (int j = b0; j < b1; j++) {
        int e = g_eperm[j];
        float v = h[(size_t)g_src[e] * K + k];
        const float* w = &g_w[e * H];
        a0 += w[0] * v; a1 += w[1] * v; a2 += w[2] * v; a3 += w[3] * v;
    }
    size_t base = (size_t)n * (H * K) + k;
    agg[base]         = a0;
    agg[base + K]     = a1;
    agg[base + 2 * K] = a2;
    agg[base + 3 * K] = a3;
}

// ------------- small GEMM (layer 1): C = A[N,K] @ B[K,NN] + bias -----------
__global__ void k_gemm_small(const float* __restrict__ A, const float* __restrict__ B,
                             const float* __restrict__ bias, float* __restrict__ C,
                             int K, int NN, int relu) {
    int idx = blockIdx.x * blockDim.x + threadIdx.x;
    int n = idx / NN, d = idx % NN;
    if (n >= N) return;
    const float* ar = A + (size_t)n * K;
    float acc = 0.f;
    for (int k = 0; k < K; k++) acc += ar[k] * B[k * NN + d];
    acc += bias[d];
    if (relu) acc = fmaxf(acc, 0.f);
    C[(size_t)n * NN + d] = acc;
}

// ------------- tf32 tensor-core GEMM: 128x128x32, 8 warps ------------------
__device__ __forceinline__ unsigned f2tf32(float x) {
    unsigned u;
    asm("cvt.rna.tf32.f32 %0, %1;" : "=r"(u) : "f"(x));
    return u;
}

__global__ void __launch_bounds__(256, 2)
k_gemm_tc(const float* __restrict__ A, const float* __restrict__ B,
          const float* __restrict__ bias, float* __restrict__ C,
          int K, int NN, int relu) {
    __shared__ unsigned As[32][132];   // [k][m], padded stride
    __shared__ unsigned Bs[32][132];   // [k][n], padded stride
    int tid = threadIdx.x;
    int wid = tid >> 5, lane = tid & 31;
    int bm = blockIdx.y * 128, bn = blockIdx.x * 128;
    int wm = (wid >> 2) * 64;          // warp row offset: 0 / 64
    int wn = (wid & 3) * 32;           // warp col offset: 0/32/64/96
    int grp = lane >> 2, tig = lane & 3;

    float c[4][4][4];
#pragma unroll
    for (int mt = 0; mt < 4; mt++)
#pragma unroll
        for (int nt = 0; nt < 4; nt++)
#pragma unroll
            for (int q = 0; q < 4; q++) c[mt][nt][q] = 0.f;

    for (int k0 = 0; k0 < K; k0 += 32) {
#pragma unroll
        for (int i = 0; i < 4; i++) {                 // A tile: 1024 float4
            int f = tid + i * 256;
            int m = f >> 3, kq = (f & 7) * 4;
            float4 v = *reinterpret_cast<const float4*>(&A[(size_t)(bm + m) * K + k0 + kq]);
            As[kq + 0][m] = f2tf32(v.x);
            As[kq + 1][m] = f2tf32(v.y);
            As[kq + 2][m] = f2tf32(v.z);
            As[kq + 3][m] = f2tf32(v.w);
        }
#pragma unroll
        for (int i = 0; i < 4; i++) {                 // B tile: 1024 float4
            int f = tid + i * 256;
            int k = f >> 5, n4 = (f & 31) * 4;
            float4 v = *reinterpret_cast<const float4*>(&B[(size_t)(k0 + k) * NN + bn + n4]);
            Bs[k][n4 + 0] = f2tf32(v.x);
            Bs[k][n4 + 1] = f2tf32(v.y);
            Bs[k][n4 + 2] = f2tf32(v.z);
            Bs[k][n4 + 3] = f2tf32(v.w);
        }
        __syncthreads();
#pragma unroll
        for (int kk = 0; kk < 32; kk += 8) {
            unsigned a[4][4], b[4][2];
#pragma unroll
            for (int mt = 0; mt < 4; mt++) {
                int mr = wm + mt * 16 + grp;
                a[mt][0] = As[kk + tig][mr];
                a[mt][1] = As[kk + tig][mr + 8];
                a[mt][2] = As[kk + tig + 4][mr];
                a[mt][3] = As[kk + tig + 4][mr + 8];
            }
#pragma unroll
            for (int nt = 0; nt < 4; nt++) {
                int nc = wn + nt * 8 + grp;
                b[nt][0] = Bs[kk + tig][nc];
                b[nt][1] = Bs[kk + tig + 4][nc];
            }
#pragma unroll
            for (int mt = 0; mt < 4; mt++)
#pragma unroll
                for (int nt = 0; nt < 4; nt++) {
                    asm volatile(
                        "mma.sync.aligned.m16n8k8.row.col.f32.tf32.tf32.f32 "
                        "{%0,%1,%2,%3}, {%4,%5,%6,%7}, {%8,%9}, {%0,%1,%2,%3};"
                        : "+f"(c[mt][nt][0]), "+f"(c[mt][nt][1]),
                          "+f"(c[mt][nt][2]), "+f"(c[mt][nt][3])
                        : "r"(a[mt][0]), "r"(a[mt][1]), "r"(a[mt][2]), "r"(a[mt][3]),
                          "r"(b[nt][0]), "r"(b[nt][1]));
                }
        }
        __syncthreads();
    }

    // epilogue: bias (+relu)
#pragma unroll
    for (int mt = 0; mt < 4; mt++) {
#pragma unroll
        for (int nt = 0; nt < 4; nt++) {
            int col = bn + wn + nt * 8 + tig * 2;
            float bv0 = bias[col], bv1 = bias[col + 1];
            int r0 = bm + wm + mt * 16 + grp;
            float v00 = c[mt][nt][0] + bv0, v01 = c[mt][nt][1] + bv1;
            float v10 = c[mt][nt][2] + bv0, v11 = c[mt][nt][3] + bv1;
            if (relu) {
                v00 = fmaxf(v00, 0.f); v01 = fmaxf(v01, 0.f);
                v10 = fmaxf(v10, 0.f); v11 = fmaxf(v11, 0.f);
            }
            C[(size_t)r0 * NN + col]           = v00;
            C[(size_t)r0 * NN + col + 1]       = v01;
            C[(size_t)(r0 + 8) * NN + col]     = v10;
            C[(size_t)(r0 + 8) * NN + col + 1] = v11;
        }
    }
}

// ---------------------------------------------------------------------------
extern "C" void kernel_launch(void* const* d_in, const int* in_sizes, int n_in,
                              void* d_out, int out_size) {
    const float* x   = (const float*)d_in[0];
    const int*   eit = (const int*)d_in[1];
    const float* W1  = (const float*)d_in[2];
    const float* We1 = (const float*)d_in[3];
    const float* as1 = (const float*)d_in[4];
    const float* ad1 = (const float*)d_in[5];
    const float* ae1 = (const float*)d_in[6];
    const float* b1  = (const float*)d_in[7];
    const float* W2  = (const float*)d_in[8];
    const float* We2 = (const float*)d_in[9];
    const float* as2 = (const float*)d_in[10];
    const float* ad2 = (const float*)d_in[11];
    const float* ae2 = (const float*)d_in[12];
    const float* b2  = (const float*)d_in[13];
    const float* W3  = (const float*)d_in[14];
    const float* We3 = (const float*)d_in[15];
    const float* as3 = (const float*)d_in[16];
    const float* ad3 = (const float*)d_in[17];
    const float* ae3 = (const float*)d_in[18];
    const float* b3  = (const float*)d_in[19];
    float* out = (float*)d_out;

    float *agg = nullptr, *hbuf = nullptr, *wst = nullptr;
    cudaGetSymbolAddress((void**)&agg, g_agg);
    cudaGetSymbolAddress((void**)&hbuf, g_hbuf);
    cudaGetSymbolAddress((void**)&wst, g_wstack);

    // ---- graph build (CSR by dst) ----
    k_zero_deg<<<N / 256, 256>>>();
    k_build<<<E / 256, 256>>>(eit);
    k_scan<<<1, 1024>>>();
    k_scatter<<<E / 256, 256>>>();

    // ---- layer 1: K=16 -> dout=32 ----
    k_prep_u<<<1, H * 16>>>(W1, as1, ad1, 16, 32);
    k_edgetable<<<1, 64>>>(We1, ae1, 32);
    k_wstack<<<(H * 16 * 32 + 255) / 256, 256>>>(W1, 16, 32);
    k_scores<<<N / 8, 256>>>(x, 16);
    k_softmax<<<(N * H) / 256, 256>>>();
    k_aggregate_in<16><<<N / 8, 128>>>(x, agg);
    k_gemm_small<<<(N * 32) / 256, 256>>>(agg, wst, b1, hbuf, H * 16, 32, 1);

    // ---- layer 2: K=32 -> dout=128 (tf32 TC GEMM) ----
    k_prep_u<<<1, H * 32>>>(W2, as2, ad2, 32, 128);
    k_edgetable<<<1, 64>>>(We2, ae2, 128);
    k_wstack<<<(H * 32 * 128 + 255) / 256, 256>>>(W2, 32, 128);
    k_scores<<<N / 8, 256>>>(hbuf, 32);
    k_softmax<<<(N * H) / 256, 256>>>();
    k_aggregate_in<32><<<N / 4, 128>>>(hbuf, agg);
    k_gemm_tc<<<dim3(1, N / 128), 256>>>(agg, wst, b2, hbuf, H * 32, 128, 1);

    // ---- layer 3: K=128 -> dout=512 (tf32 TC GEMM, writes d_out) ----
    k_prep_u<<<2, 256>>>(W3, as3, ad3, 128, 512);
    k_edgetable<<<1, 64>>>(We3, ae3, 512);
    k_wstack<<<(H * 128 * 512 + 255) / 256, 256>>>(W3, 128, 512);
    k_scores<<<N / 8, 256>>>(hbuf, 128);
    k_softmax<<<(N * H) / 256, 256>>>();
    k_aggregate_in<128><<<N, 128>>>(hbuf, agg);
    k_gemm_tc<<<dim3(4, N / 128), 256>>>(agg, wst, b3, out, H * 128, 512, 0);
}

// round 4
// speedup vs baseline: 2.5333x; 1.0815x over previous
#include <cuda_runtime.h>

constexpr int N    = 32768;
constexpr int EPER = 16384;
constexpr int T    = 8;
constexpr int E0   = T * EPER;   // 131072 typed edges
constexpr int E    = E0 + N;     // + self loops = 163840
constexpr int H    = 4;
constexpr float NEG = 0.2f;

// ---------------------------- scratch (device globals) ---------------------
__device__ float g_agg[(size_t)N * 512];    // input-space aggregation [N, H*K] (tf32-rounded for L2/L3)
__device__ float g_hbuf[(size_t)N * 128];   // inter-layer activations (fp32)
__device__ float g_ssrc[N * H];
__device__ float g_sdst[N * H];
__device__ float g_w[E * H];                // edge attention weights
__device__ float g_etab[(T + 1) * H];
__device__ float g_usrc[H * 128];
__device__ float g_udst[H * 128];
__device__ float g_wstack[512 * 512];       // [H*K, dout] head-blocked W/H (tf32-rounded for L2/L3)
__device__ int   g_src[E], g_dst[E], g_et[E];
__device__ int   g_deg[N], g_rowptr[N + 1], g_fill[N], g_eperm[E];

__device__ __forceinline__ float tf32r(float x) {
    unsigned u;
    asm("cvt.rna.tf32.f32 %0, %1;" : "=r"(u) : "f"(x));
    return __uint_as_float(u);
}

// ---------------------------- graph build (CSR by dst) ---------------------
__global__ void k_zero_deg() {
    int i = blockIdx.x * blockDim.x + threadIdx.x;
    if (i < N) g_deg[i] = 0;
}

__global__ void k_build(const int* __restrict__ eit) {
    int e = blockIdx.x * blockDim.x + threadIdx.x;
    if (e >= E) return;
    int s, d, t;
    if (e < E0) {
        t = e / EPER;
        int i = e - t * EPER;
        s = eit[t * 2 * EPER + i];
        d = eit[t * 2 * EPER + EPER + i];
    } else {
        s = d = e - E0;
        t = T;
    }
    g_src[e] = s; g_dst[e] = d; g_et[e] = t;
    atomicAdd(&g_deg[d], 1);
}

__global__ void k_scan() {
    __shared__ int sh[1024];
    int t = threadIdx.x;
    int base = t * 32;
    int loc[32];
    int sum = 0;
#pragma unroll
    for (int i = 0; i < 32; i++) { loc[i] = sum; sum += g_deg[base + i]; }
    sh[t] = sum;
    __syncthreads();
    for (int off = 1; off < 1024; off <<= 1) {
        int v = (t >= off) ? sh[t - off] : 0;
        __syncthreads();
        if (t >= off) sh[t] += v;
        __syncthreads();
    }
    int prev = (t == 0) ? 0 : sh[t - 1];
#pragma unroll
    for (int i = 0; i < 32; i++) {
        int v = prev + loc[i];
        g_rowptr[base + i] = v;
        g_fill[base + i]   = v;
    }
    if (t == 1023) g_rowptr[N] = sh[1023];
}

__global__ void k_scatter() {
    int e = blockIdx.x * blockDim.x + threadIdx.x;
    if (e >= E) return;
    int pos = atomicAdd(&g_fill[g_dst[e]], 1);
    g_eperm[pos] = e;
}

// ------------- fused per-layer prep: wstack + U vectors + edge table -------
// blocks [0, wblocks): wstack   block wblocks: U   block wblocks+1: edgetable
__global__ void k_prep(const float* __restrict__ W, const float* __restrict__ asrc,
                       const float* __restrict__ adst, const float* __restrict__ We,
                       const float* __restrict__ ae, int K, int dout, int wblocks,
                       int cvt) {
    __shared__ float sh[T][H];
    int b = blockIdx.x, tid = threadIdx.x;
    if (b < wblocks) {
        int idx = b * 256 + tid;
        if (idx < H * K * dout) {
            int d = idx % dout;
            int hk = idx / dout;
            int h = hk / K, k = hk % K;
            float v = W[(size_t)k * (H * dout) + h * dout + d] * 0.25f;
            g_wstack[idx] = cvt ? tf32r(v) : v;
        }
    } else if (b == wblocks) {
        for (int idx = tid; idx < H * K; idx += 256) {
            int h = idx / K, k = idx % K;
            const float* wr = W + (size_t)k * (H * dout) + h * dout;
            const float* as = asrc + h * dout;
            const float* ad = adst + h * dout;
            float vs = 0.f, vd = 0.f;
            for (int d = 0; d < dout; d++) { vs += wr[d] * as[d]; vd += wr[d] * ad[d]; }
            g_usrc[idx] = vs;
            g_udst[idx] = vd;
        }
    } else {
        int HC = H * dout;
        if (tid < T * H) {
            int t = tid >> 2, h = tid & 3;
            float s = 0.f;
            for (int c = 0; c < dout; c++) s += We[t * HC + h * dout + c] * ae[h * dout + c];
            sh[t][h] = s;
            g_etab[t * H + h] = s;
        }
        __syncthreads();
        if (tid < H) {
            float s = 0.f;
            for (int t = 0; t < T; t++) s += sh[t][tid];
            g_etab[T * H + tid] = s * (1.0f / T);
        }
    }
}

// ---------------------------- per-node attention scores --------------------
__global__ void k_scores(const float* __restrict__ h, int K) {
    int gw = (blockIdx.x * blockDim.x + threadIdx.x) >> 5;
    int lane = threadIdx.x & 31;
    if (gw >= N) return;
    const float* row = h + (size_t)gw * K;
    float acc[2][H];
#pragma unroll
    for (int i = 0; i < 2; i++)
#pragma unroll
        for (int hh = 0; hh < H; hh++) acc[i][hh] = 0.f;
    for (int k = lane; k < K; k += 32) {
        float x = row[k];
#pragma unroll
        for (int hh = 0; hh < H; hh++) {
            acc[0][hh] += x * g_usrc[hh * K + k];
            acc[1][hh] += x * g_udst[hh * K + k];
        }
    }
#pragma unroll
    for (int i = 0; i < 2; i++)
#pragma unroll
        for (int hh = 0; hh < H; hh++)
#pragma unroll
            for (int o = 16; o > 0; o >>= 1)
                acc[i][hh] += __shfl_xor_sync(0xffffffffu, acc[i][hh], o);
    if (lane < H)      g_ssrc[gw * H + lane] = acc[0][lane];
    else if (lane < 2 * H) g_sdst[gw * H + (lane - H)] = acc[1][lane - H];
}

// ---------------------------- segment softmax over dst ---------------------
__global__ void k_softmax() {
    int idx = blockIdx.x * blockDim.x + threadIdx.x;
    if (idx >= N * H) return;
    int n = idx >> 2, h = idx & 3;
    int b0 = g_rowptr[n], b1 = g_rowptr[n + 1];
    float sd = g_sdst[idx];
    float mx = -1e30f;
    for (int j = b0; j < b1; j++) {
        int e = g_eperm[j];
        float a = g_ssrc[g_src[e] * H + h] + sd + g_etab[g_et[e] * H + h];
        a = (a > 0.f) ? a : NEG * a;
        g_w[e * H + h] = a;
        mx = fmaxf(mx, a);
    }
    float s = 0.f;
    for (int j = b0; j < b1; j++) {
        int e = g_eperm[j];
        float ex = expf(g_w[e * H + h] - mx);
        g_w[e * H + h] = ex;
        s += ex;
    }
    float inv = 1.f / s;
    for (int j = b0; j < b1; j++) {
        int e = g_eperm[j];
        g_w[e * H + h] *= inv;
    }
}

// ---------------- input-space aggregation: agg[n, h*K+k] -------------------
template <int K, bool CVT>
__global__ void k_aggregate_in(const float* __restrict__ h, float* __restrict__ agg) {
    constexpr int NPB = 128 / K;
    int tid = threadIdx.x;
    int n = blockIdx.x * NPB + tid / K;
    int k = tid % K;
    int b0 = g_rowptr[n], b1 = g_rowptr[n + 1];
    float a0 = 0.f, a1 = 0.f, a2 = 0.f, a3 = 0.f;
    for (int j = b0; j < b1; j++) {
        int e = g_eperm[j];
        float v = h[(size_t)g_src[e] * K + k];
        const float* w = &g_w[e * H];
        a0 += w[0] * v; a1 += w[1] * v; a2 += w[2] * v; a3 += w[3] * v;
    }
    if (CVT) { a0 = tf32r(a0); a1 = tf32r(a1); a2 = tf32r(a2); a3 = tf32r(a3); }
    size_t base = (size_t)n * (H * K) + k;
    agg[base]         = a0;
    agg[base + K]     = a1;
    agg[base + 2 * K] = a2;
    agg[base + 3 * K] = a3;
}

// ------------- small GEMM (layer 1): C = A[N,K] @ B[K,NN] + bias -----------
__global__ void k_gemm_small(const float* __restrict__ A, const float* __restrict__ B,
                             const float* __restrict__ bias, float* __restrict__ C,
                             int K, int NN, int relu) {
    int idx = blockIdx.x * blockDim.x + threadIdx.x;
    int n = idx / NN, d = idx % NN;
    if (n >= N) return;
    const float* ar = A + (size_t)n * K;
    float acc = 0.f;
    for (int k = 0; k < K; k++) acc += ar[k] * B[k * NN + d];
    acc += bias[d];
    if (relu) acc = fmaxf(acc, 0.f);
    C[(size_t)n * NN + d] = acc;
}

// ------- tf32 TC GEMM: 128x128x32, cp.async 2-stage double buffer ----------
// A, B hold pre-rounded tf32 bit patterns. Conflict-free smem layouts:
//   As[m][k] stride 36  -> fragment bank = 4*grp + tig (perm)
//   Bs[k][n] stride 136 -> fragment bank = 8*tig + grp (perm)
constexpr int SMEM_GEMM = (2 * 128 * 36 + 2 * 32 * 136) * 4;   // 71680 B

__global__ void __launch_bounds__(256, 2)
k_gemm_tc(const float* __restrict__ A, const float* __restrict__ B,
          const float* __restrict__ bias, float* __restrict__ C,
          int K, int NN, int relu) {
    extern __shared__ float sm[];
    float (*As)[128][36] = reinterpret_cast<float (*)[128][36]>(sm);
    float (*Bs)[32][136] = reinterpret_cast<float (*)[32][136]>(sm + 2 * 128 * 36);
    int tid = threadIdx.x;
    int wid = tid >> 5, lane = tid & 31;
    int bm = blockIdx.y * 128, bn = blockIdx.x * 128;
    int wm = (wid >> 2) * 64;
    int wn = (wid & 3) * 32;
    int grp = lane >> 2, tig = lane & 3;

    float c[4][4][4];
#pragma unroll
    for (int mt = 0; mt < 4; mt++)
#pragma unroll
        for (int nt = 0; nt < 4; nt++)
#pragma unroll
            for (int q = 0; q < 4; q++) c[mt][nt][q] = 0.f;

    int nk = K >> 5;

    auto copy_tile = [&](int s, int k0) {
#pragma unroll
        for (int i = 0; i < 4; i++) {
            int f = tid + i * 256;
            int m = f >> 3, kq = (f & 7) * 4;
            unsigned dst = (unsigned)__cvta_generic_to_shared(&As[s][m][kq]);
            const float* src = &A[(size_t)(bm + m) * K + k0 + kq];
            asm volatile("cp.async.ca.shared.global [%0], [%1], 16;" :: "r"(dst), "l"(src));
        }
#pragma unroll
        for (int i = 0; i < 4; i++) {
            int f = tid + i * 256;
            int k = f >> 5, n4 = (f & 31) * 4;
            unsigned dst = (unsigned)__cvta_generic_to_shared(&Bs[s][k][n4]);
            const float* src = &B[(size_t)(k0 + k) * NN + bn + n4];
            asm volatile("cp.async.ca.shared.global [%0], [%1], 16;" :: "r"(dst), "l"(src));
        }
        asm volatile("cp.async.commit_group;");
    };

    copy_tile(0, 0);

    for (int it = 0; it < nk; it++) {
        int cur = it & 1;
        if (it + 1 < nk) {
            copy_tile(cur ^ 1, (it + 1) * 32);
            asm volatile("cp.async.wait_group 1;");
        } else {
            asm volatile("cp.async.wait_group 0;");
        }
        __syncthreads();
#pragma unroll
        for (int kk = 0; kk < 32; kk += 8) {
            unsigned a[4][4], b[4][2];
#pragma unroll
            for (int mt = 0; mt < 4; mt++) {
                int mr = wm + mt * 16 + grp;
                a[mt][0] = __float_as_uint(As[cur][mr][kk + tig]);
                a[mt][1] = __float_as_uint(As[cur][mr + 8][kk + tig]);
                a[mt][2] = __float_as_uint(As[cur][mr][kk + tig + 4]);
                a[mt][3] = __float_as_uint(As[cur][mr + 8][kk + tig + 4]);
            }
#pragma unroll
            for (int nt = 0; nt < 4; nt++) {
                int nc = wn + nt * 8 + grp;
                b[nt][0] = __float_as_uint(Bs[cur][kk + tig][nc]);
                b[nt][1] = __float_as_uint(Bs[cur][kk + tig + 4][nc]);
            }
#pragma unroll
            for (int mt = 0; mt < 4; mt++)
#pragma unroll
                for (int nt = 0; nt < 4; nt++) {
                    asm volatile(
                        "mma.sync.aligned.m16n8k8.row.col.f32.tf32.tf32.f32 "
                        "{%0,%1,%2,%3}, {%4,%5,%6,%7}, {%8,%9}, {%0,%1,%2,%3};"
                        : "+f"(c[mt][nt][0]), "+f"(c[mt][nt][1]),
                          "+f"(c[mt][nt][2]), "+f"(c[mt][nt][3])
                        : "r"(a[mt][0]), "r"(a[mt][1]), "r"(a[mt][2]), "r"(a[mt][3]),
                          "r"(b[nt][0]), "r"(b[nt][1]));
                }
        }
        __syncthreads();
    }

    // epilogue: bias (+relu)
#pragma unroll
    for (int mt = 0; mt < 4; mt++) {
#pragma unroll
        for (int nt = 0; nt < 4; nt++) {
            int col = bn + wn + nt * 8 + tig * 2;
            float bv0 = bias[col], bv1 = bias[col + 1];
            int r0 = bm + wm + mt * 16 + grp;
            float v00 = c[mt][nt][0] + bv0, v01 = c[mt][nt][1] + bv1;
            float v10 = c[mt][nt][2] + bv0, v11 = c[mt][nt][3] + bv1;
            if (relu) {
                v00 = fmaxf(v00, 0.f); v01 = fmaxf(v01, 0.f);
                v10 = fmaxf(v10, 0.f); v11 = fmaxf(v11, 0.f);
            }
            C[(size_t)r0 * NN + col]           = v00;
            C[(size_t)r0 * NN + col + 1]       = v01;
            C[(size_t)(r0 + 8) * NN + col]     = v10;
            C[(size_t)(r0 + 8) * NN + col + 1] = v11;
        }
    }
}

// ---------------------------------------------------------------------------
extern "C" void kernel_launch(void* const* d_in, const int* in_sizes, int n_in,
                              void* d_out, int out_size) {
    const float* x   = (const float*)d_in[0];
    const int*   eit = (const int*)d_in[1];
    const float* W1  = (const float*)d_in[2];
    const float* We1 = (const float*)d_in[3];
    const float* as1 = (const float*)d_in[4];
    const float* ad1 = (const float*)d_in[5];
    const float* ae1 = (const float*)d_in[6];
    const float* b1  = (const float*)d_in[7];
    const float* W2  = (const float*)d_in[8];
    const float* We2 = (const float*)d_in[9];
    const float* as2 = (const float*)d_in[10];
    const float* ad2 = (const float*)d_in[11];
    const float* ae2 = (const float*)d_in[12];
    const float* b2  = (const float*)d_in[13];
    const float* W3  = (const float*)d_in[14];
    const float* We3 = (const float*)d_in[15];
    const float* as3 = (const float*)d_in[16];
    const float* ad3 = (const float*)d_in[17];
    const float* ae3 = (const float*)d_in[18];
    const float* b3  = (const float*)d_in[19];
    float* out = (float*)d_out;

    float *agg = nullptr, *hbuf = nullptr, *wst = nullptr;
    cudaGetSymbolAddress((void**)&agg, g_agg);
    cudaGetSymbolAddress((void**)&hbuf, g_hbuf);
    cudaGetSymbolAddress((void**)&wst, g_wstack);

    cudaFuncSetAttribute(k_gemm_tc, cudaFuncAttributeMaxDynamicSharedMemorySize, SMEM_GEMM);

    // ---- graph build (CSR by dst) ----
    k_zero_deg<<<N / 256, 256>>>();
    k_build<<<E / 256, 256>>>(eit);
    k_scan<<<1, 1024>>>();
    k_scatter<<<E / 256, 256>>>();

    // ---- layer 1: K=16 -> dout=32 (fp32 SIMT path) ----
    {
        int wb = (H * 16 * 32 + 255) / 256;
        k_prep<<<wb + 2, 256>>>(W1, as1, ad1, We1, ae1, 16, 32, wb, 0);
    }
    k_scores<<<N / 8, 256>>>(x, 16);
    k_softmax<<<(N * H) / 256, 256>>>();
    k_aggregate_in<16, false><<<N / 8, 128>>>(x, agg);
    k_gemm_small<<<(N * 32) / 256, 256>>>(agg, wst, b1, hbuf, H * 16, 32, 1);

    // ---- layer 2: K=32 -> dout=128 (tf32 TC GEMM) ----
    {
        int wb = (H * 32 * 128 + 255) / 256;
        k_prep<<<wb + 2, 256>>>(W2, as2, ad2, We2, ae2, 32, 128, wb, 1);
    }
    k_scores<<<N / 8, 256>>>(hbuf, 32);
    k_softmax<<<(N * H) / 256, 256>>>();
    k_aggregate_in<32, true><<<N / 4, 128>>>(hbuf, agg);
    k_gemm_tc<<<dim3(1, N / 128), 256, SMEM_GEMM>>>(agg, wst, b2, hbuf, H * 32, 128, 1);

    // ---- layer 3: K=128 -> dout=512 (tf32 TC GEMM, writes d_out) ----
    {
        int wb = (H * 128 * 512 + 255) / 256;
        k_prep<<<wb + 2, 256>>>(W3, as3, ad3, We3, ae3, 128, 512, wb, 1);
    }
    k_scores<<<N / 8, 256>>>(hbuf, 128);
    k_softmax<<<(N * H) / 256, 256>>>();
    k_aggregate_in<128, true><<<N, 128>>>(hbuf, agg);
    k_gemm_tc<<<dim3(4, N / 128), 256, SMEM_GEMM>>>(agg, wst, b3, out, H * 128, 512, 0);
}

// round 5
// speedup vs baseline: 2.5400x; 1.0027x over previous
#include <cuda_runtime.h>

constexpr int N    = 32768;
constexpr int EPER = 16384;
constexpr int T    = 8;
constexpr int E0   = T * EPER;   // 131072 typed edges
constexpr int E    = E0 + N;     // + self loops = 163840
constexpr int H    = 4;
constexpr float NEG = 0.2f;

// ---------------------------- scratch (device globals) ---------------------
__device__ float g_agg[(size_t)N * 512];    // input-space aggregation [N, H*K]
__device__ float g_hbuf[(size_t)N * 128];   // inter-layer activations (fp32)
__device__ float g_ssrc[N * H];
__device__ float g_sdst[N * H];
__device__ float g_etab[(T + 1) * H];
__device__ float g_usrc[H * 128];
__device__ float g_udst[H * 128];
__device__ float g_wstack[512 * 512];       // [H*K, dout] head-blocked W/H
__device__ int   g_se[E];                   // dst-sorted packed edges: src | (et<<20)
__device__ int   g_src[E], g_dst[E], g_et[E];
__device__ int   g_deg[N], g_rowptr[N + 1], g_fill[N];

__device__ __forceinline__ float tf32r(float x) {
    unsigned u;
    asm("cvt.rna.tf32.f32 %0, %1;" : "=r"(u) : "f"(x));
    return __uint_as_float(u);
}

// ---------------------------- graph build (CSR by dst) ---------------------
__global__ void k_zero_deg() {
    int i = blockIdx.x * blockDim.x + threadIdx.x;
    if (i < N) g_deg[i] = 0;
}

__global__ void k_build(const int* __restrict__ eit) {
    int e = blockIdx.x * blockDim.x + threadIdx.x;
    if (e >= E) return;
    int s, d, t;
    if (e < E0) {
        t = e / EPER;
        int i = e - t * EPER;
        s = eit[t * 2 * EPER + i];
        d = eit[t * 2 * EPER + EPER + i];
    } else {
        s = d = e - E0;
        t = T;
    }
    g_src[e] = s; g_dst[e] = d; g_et[e] = t;
    atomicAdd(&g_deg[d], 1);
}

__global__ void k_scan() {
    __shared__ int sh[1024];
    int t = threadIdx.x;
    int base = t * 32;
    int loc[32];
    int sum = 0;
#pragma unroll
    for (int i = 0; i < 32; i++) { loc[i] = sum; sum += g_deg[base + i]; }
    sh[t] = sum;
    __syncthreads();
    for (int off = 1; off < 1024; off <<= 1) {
        int v = (t >= off) ? sh[t - off] : 0;
        __syncthreads();
        if (t >= off) sh[t] += v;
        __syncthreads();
    }
    int prev = (t == 0) ? 0 : sh[t - 1];
#pragma unroll
    for (int i = 0; i < 32; i++) {
        int v = prev + loc[i];
        g_rowptr[base + i] = v;
        g_fill[base + i]   = v;
    }
    if (t == 1023) g_rowptr[N] = sh[1023];
}

__global__ void k_scatter() {
    int e = blockIdx.x * blockDim.x + threadIdx.x;
    if (e >= E) return;
    int pos = atomicAdd(&g_fill[g_dst[e]], 1);
    g_se[pos] = g_src[e] | (g_et[e] << 20);
}

// ------------- fused per-layer prep: wstack + U vectors + edge table -------
__global__ void k_prep(const float* __restrict__ W, const float* __restrict__ asrc,
                       const float* __restrict__ adst, const float* __restrict__ We,
                       const float* __restrict__ ae, int K, int dout, int wblocks,
                       int cvt) {
    __shared__ float sh[T][H];
    int b = blockIdx.x, tid = threadIdx.x;
    if (b < wblocks) {
        int idx = b * 256 + tid;
        if (idx < H * K * dout) {
            int d = idx % dout;
            int hk = idx / dout;
            int h = hk / K, k = hk % K;
            float v = W[(size_t)k * (H * dout) + h * dout + d] * 0.25f;
            g_wstack[idx] = cvt ? tf32r(v) : v;
        }
    } else if (b == wblocks) {
        for (int idx = tid; idx < H * K; idx += 256) {
            int h = idx / K, k = idx % K;
            const float* wr = W + (size_t)k * (H * dout) + h * dout;
            const float* as = asrc + h * dout;
            const float* ad = adst + h * dout;
            float vs = 0.f, vd = 0.f;
            for (int d = 0; d < dout; d++) { vs += wr[d] * as[d]; vd += wr[d] * ad[d]; }
            g_usrc[idx] = vs;
            g_udst[idx] = vd;
        }
    } else {
        int HC = H * dout;
        if (tid < T * H) {
            int t = tid >> 2, h = tid & 3;
            float s = 0.f;
            for (int c = 0; c < dout; c++) s += We[t * HC + h * dout + c] * ae[h * dout + c];
            sh[t][h] = s;
            g_etab[t * H + h] = s;
        }
        __syncthreads();
        if (tid < H) {
            float s = 0.f;
            for (int t = 0; t < T; t++) s += sh[t][tid];
            g_etab[T * H + tid] = s * (1.0f / T);
        }
    }
}

// ---------------------------- per-node attention scores --------------------
__global__ void k_scores(const float* __restrict__ h, int K) {
    int gw = (blockIdx.x * blockDim.x + threadIdx.x) >> 5;
    int lane = threadIdx.x & 31;
    if (gw >= N) return;
    const float* row = h + (size_t)gw * K;
    float acc[2][H];
#pragma unroll
    for (int i = 0; i < 2; i++)
#pragma unroll
        for (int hh = 0; hh < H; hh++) acc[i][hh] = 0.f;
    for (int k = lane; k < K; k += 32) {
        float x = row[k];
#pragma unroll
        for (int hh = 0; hh < H; hh++) {
            acc[0][hh] += x * g_usrc[hh * K + k];
            acc[1][hh] += x * g_udst[hh * K + k];
        }
    }
#pragma unroll
    for (int i = 0; i < 2; i++)
#pragma unroll
        for (int hh = 0; hh < H; hh++)
#pragma unroll
            for (int o = 16; o > 0; o >>= 1)
                acc[i][hh] += __shfl_xor_sync(0xffffffffu, acc[i][hh], o);
    if (lane < H)      g_ssrc[gw * H + lane] = acc[0][lane];
    else if (lane < 2 * H) g_sdst[gw * H + (lane - H)] = acc[1][lane - H];
}

// ------- fused alpha + online softmax + aggregation ------------------------
// K==128: one node per 128-thread block (__syncthreads).
// K<=32 : one node per warp, 4 warps per block (__syncwarp).
template <int K, bool CVT>
__global__ void k_gat_edge(const float* __restrict__ h, float* __restrict__ agg) {
    constexpr int CH = 32;
    constexpr bool BN = (K == 128);          // block-per-node
    __shared__ float s_w[BN ? 1 : 4][CH][H];
    __shared__ int   s_pk[BN ? 1 : 4][CH];

    int grp  = BN ? 0 : (threadIdx.x >> 5);
    int gtid = BN ? threadIdx.x : (threadIdx.x & 31);
    int n    = BN ? blockIdx.x : (blockIdx.x * 4 + grp);
    int b0 = g_rowptr[n], b1 = g_rowptr[n + 1];

    // ---- phase A: online softmax stats (4 head threads per node) ----
    float m = -1e30f, s = 0.f;
    if (gtid < H) {
        float sd = g_sdst[n * H + gtid];
        for (int j = b0; j < b1; j++) {
            int p = g_se[j];
            int src = p & 0xFFFFF, et = p >> 20;
            float a = g_ssrc[src * H + gtid] + sd + g_etab[et * H + gtid];
            a = (a > 0.f) ? a : NEG * a;
            float mn = fmaxf(m, a);
            s = s * __expf(m - mn) + __expf(a - mn);
            m = mn;
        }
        s = 1.f / s;
    }

    // ---- phase B: chunked weight materialization + aggregation ----
    float a0 = 0.f, a1 = 0.f, a2 = 0.f, a3 = 0.f;
    for (int j0 = b0; j0 < b1; j0 += CH) {
        int cnt = min(CH, b1 - j0);
        if (gtid < cnt) s_pk[grp][gtid] = g_se[j0 + gtid];
        if (BN) __syncthreads(); else __syncwarp();
        if (gtid < H) {
            float sd = g_sdst[n * H + gtid];
            for (int jj = 0; jj < cnt; jj++) {
                int p = s_pk[grp][jj];
                int src = p & 0xFFFFF, et = p >> 20;
                float a = g_ssrc[src * H + gtid] + sd + g_etab[et * H + gtid];
                a = (a > 0.f) ? a : NEG * a;
                s_w[grp][jj][gtid] = __expf(a - m) * s;
            }
        }
        if (BN) __syncthreads(); else __syncwarp();
        if (gtid < K) {
            for (int jj = 0; jj < cnt; jj++) {
                int src = s_pk[grp][jj] & 0xFFFFF;
                float v = h[(size_t)src * K + gtid];
                a0 += s_w[grp][jj][0] * v;
                a1 += s_w[grp][jj][1] * v;
                a2 += s_w[grp][jj][2] * v;
                a3 += s_w[grp][jj][3] * v;
            }
        }
        if (BN) __syncthreads(); else __syncwarp();
    }

    if (gtid < K) {
        if (CVT) { a0 = tf32r(a0); a1 = tf32r(a1); a2 = tf32r(a2); a3 = tf32r(a3); }
        size_t base = (size_t)n * (H * K) + gtid;
        agg[base]         = a0;
        agg[base + K]     = a1;
        agg[base + 2 * K] = a2;
        agg[base + 3 * K] = a3;
    }
}

// ------------- small GEMM (layer 1): C = A[N,K] @ B[K,NN] + bias -----------
__global__ void k_gemm_small(const float* __restrict__ A, const float* __restrict__ B,
                             const float* __restrict__ bias, float* __restrict__ C,
                             int K, int NN, int relu) {
    int idx = blockIdx.x * blockDim.x + threadIdx.x;
    int n = idx / NN, d = idx % NN;
    if (n >= N) return;
    const float* ar = A + (size_t)n * K;
    float acc = 0.f;
    for (int k = 0; k < K; k++) acc += ar[k] * B[k * NN + d];
    acc += bias[d];
    if (relu) acc = fmaxf(acc, 0.f);
    C[(size_t)n * NN + d] = acc;
}

// ------- tf32 TC GEMM: 128x128x32, cp.async 2-stage double buffer ----------
constexpr int SMEM_GEMM = (2 * 128 * 36 + 2 * 32 * 136) * 4;   // 71680 B

__global__ void __launch_bounds__(256, 2)
k_gemm_tc(const float* __restrict__ A, const float* __restrict__ B,
          const float* __restrict__ bias, float* __restrict__ C,
          int K, int NN, int relu) {
    extern __shared__ float sm[];
    float (*As)[128][36] = reinterpret_cast<float (*)[128][36]>(sm);
    float (*Bs)[32][136] = reinterpret_cast<float (*)[32][136]>(sm + 2 * 128 * 36);
    int tid = threadIdx.x;
    int wid = tid >> 5, lane = tid & 31;
    int bm = blockIdx.y * 128, bn = blockIdx.x * 128;
    int wm = (wid >> 2) * 64;
    int wn = (wid & 3) * 32;
    int grp = lane >> 2, tig = lane & 3;

    float c[4][4][4];
#pragma unroll
    for (int mt = 0; mt < 4; mt++)
#pragma unroll
        for (int nt = 0; nt < 4; nt++)
#pragma unroll
            for (int q = 0; q < 4; q++) c[mt][nt][q] = 0.f;

    int nk = K >> 5;

    auto copy_tile = [&](int s, int k0) {
#pragma unroll
        for (int i = 0; i < 4; i++) {
            int f = tid + i * 256;
            int m = f >> 3, kq = (f & 7) * 4;
            unsigned dst = (unsigned)__cvta_generic_to_shared(&As[s][m][kq]);
            const float* src = &A[(size_t)(bm + m) * K + k0 + kq];
            asm volatile("cp.async.ca.shared.global [%0], [%1], 16;" :: "r"(dst), "l"(src));
        }
#pragma unroll
        for (int i = 0; i < 4; i++) {
            int f = tid + i * 256;
            int k = f >> 5, n4 = (f & 31) * 4;
            unsigned dst = (unsigned)__cvta_generic_to_shared(&Bs[s][k][n4]);
            const float* src = &B[(size_t)(k0 + k) * NN + bn + n4];
            asm volatile("cp.async.ca.shared.global [%0], [%1], 16;" :: "r"(dst), "l"(src));
        }
        asm volatile("cp.async.commit_group;");
    };

    copy_tile(0, 0);

    for (int it = 0; it < nk; it++) {
        int cur = it & 1;
        if (it + 1 < nk) {
            copy_tile(cur ^ 1, (it + 1) * 32);
            asm volatile("cp.async.wait_group 1;");
        } else {
            asm volatile("cp.async.wait_group 0;");
        }
        __syncthreads();
#pragma unroll
        for (int kk = 0; kk < 32; kk += 8) {
            unsigned a[4][4], b[4][2];
#pragma unroll
            for (int mt = 0; mt < 4; mt++) {
                int mr = wm + mt * 16 + grp;
                a[mt][0] = __float_as_uint(As[cur][mr][kk + tig]);
                a[mt][1] = __float_as_uint(As[cur][mr + 8][kk + tig]);
                a[mt][2] = __float_as_uint(As[cur][mr][kk + tig + 4]);
                a[mt][3] = __float_as_uint(As[cur][mr + 8][kk + tig + 4]);
            }
#pragma unroll
            for (int nt = 0; nt < 4; nt++) {
                int nc = wn + nt * 8 + grp;
                b[nt][0] = __float_as_uint(Bs[cur][kk + tig][nc]);
                b[nt][1] = __float_as_uint(Bs[cur][kk + tig + 4][nc]);
            }
#pragma unroll
            for (int mt = 0; mt < 4; mt++)
#pragma unroll
                for (int nt = 0; nt < 4; nt++) {
                    asm volatile(
                        "mma.sync.aligned.m16n8k8.row.col.f32.tf32.tf32.f32 "
                        "{%0,%1,%2,%3}, {%4,%5,%6,%7}, {%8,%9}, {%0,%1,%2,%3};"
                        : "+f"(c[mt][nt][0]), "+f"(c[mt][nt][1]),
                          "+f"(c[mt][nt][2]), "+f"(c[mt][nt][3])
                        : "r"(a[mt][0]), "r"(a[mt][1]), "r"(a[mt][2]), "r"(a[mt][3]),
                          "r"(b[nt][0]), "r"(b[nt][1]));
                }
        }
        __syncthreads();
    }

#pragma unroll
    for (int mt = 0; mt < 4; mt++) {
#pragma unroll
        for (int nt = 0; nt < 4; nt++) {
            int col = bn + wn + nt * 8 + tig * 2;
            float bv0 = bias[col], bv1 = bias[col + 1];
            int r0 = bm + wm + mt * 16 + grp;
            float v00 = c[mt][nt][0] + bv0, v01 = c[mt][nt][1] + bv1;
            float v10 = c[mt][nt][2] + bv0, v11 = c[mt][nt][3] + bv1;
            if (relu) {
                v00 = fmaxf(v00, 0.f); v01 = fmaxf(v01, 0.f);
                v10 = fmaxf(v10, 0.f); v11 = fmaxf(v11, 0.f);
            }
            C[(size_t)r0 * NN + col]           = v00;
            C[(size_t)r0 * NN + col + 1]       = v01;
            C[(size_t)(r0 + 8) * NN + col]     = v10;
            C[(size_t)(r0 + 8) * NN + col + 1] = v11;
        }
    }
}

// ---------------------------------------------------------------------------
extern "C" void kernel_launch(void* const* d_in, const int* in_sizes, int n_in,
                              void* d_out, int out_size) {
    const float* x   = (const float*)d_in[0];
    const int*   eit = (const int*)d_in[1];
    const float* W1  = (const float*)d_in[2];
    const float* We1 = (const float*)d_in[3];
    const float* as1 = (const float*)d_in[4];
    const float* ad1 = (const float*)d_in[5];
    const float* ae1 = (const float*)d_in[6];
    const float* b1  = (const float*)d_in[7];
    const float* W2  = (const float*)d_in[8];
    const float* We2 = (const float*)d_in[9];
    const float* as2 = (const float*)d_in[10];
    const float* ad2 = (const float*)d_in[11];
    const float* ae2 = (const float*)d_in[12];
    const float* b2  = (const float*)d_in[13];
    const float* W3  = (const float*)d_in[14];
    const float* We3 = (const float*)d_in[15];
    const float* as3 = (const float*)d_in[16];
    const float* ad3 = (const float*)d_in[17];
    const float* ae3 = (const float*)d_in[18];
    const float* b3  = (const float*)d_in[19];
    float* out = (float*)d_out;

    float *agg = nullptr, *hbuf = nullptr, *wst = nullptr;
    cudaGetSymbolAddress((void**)&agg, g_agg);
    cudaGetSymbolAddress((void**)&hbuf, g_hbuf);
    cudaGetSymbolAddress((void**)&wst, g_wstack);

    cudaFuncSetAttribute(k_gemm_tc, cudaFuncAttributeMaxDynamicSharedMemorySize, SMEM_GEMM);

    // ---- graph build (CSR by dst, packed sorted edges) ----
    k_zero_deg<<<N / 256, 256>>>();
    k_build<<<E / 256, 256>>>(eit);
    k_scan<<<1, 1024>>>();
    k_scatter<<<E / 256, 256>>>();

    // ---- layer 1: K=16 -> dout=32 (fp32 SIMT path) ----
    {
        int wb = (H * 16 * 32 + 255) / 256;
        k_prep<<<wb + 2, 256>>>(W1, as1, ad1, We1, ae1, 16, 32, wb, 0);
    }
    k_scores<<<N / 8, 256>>>(x, 16);
    k_gat_edge<16, false><<<N / 4, 128>>>(x, agg);
    k_gemm_small<<<(N * 32) / 256, 256>>>(agg, wst, b1, hbuf, H * 16, 32, 1);

    // ---- layer 2: K=32 -> dout=128 (tf32 TC GEMM) ----
    {
        int wb = (H * 32 * 128 + 255) / 256;
        k_prep<<<wb + 2, 256>>>(W2, as2, ad2, We2, ae2, 32, 128, wb, 1);
    }
    k_scores<<<N / 8, 256>>>(hbuf, 32);
    k_gat_edge<32, true><<<N / 4, 128>>>(hbuf, agg);
    k_gemm_tc<<<dim3(1, N / 128), 256, SMEM_GEMM>>>(agg, wst, b2, hbuf, H * 32, 128, 1);

    // ---- layer 3: K=128 -> dout=512 (tf32 TC GEMM, writes d_out) ----
    {
        int wb = (H * 128 * 512 + 255) / 256;
        k_prep<<<wb + 2, 256>>>(W3, as3, ad3, We3, ae3, 128, 512, wb, 1);
    }
    k_scores<<<N / 8, 256>>>(hbuf, 128);
    k_gat_edge<128, true><<<N, 128>>>(hbuf, agg);
    k_gemm_tc<<<dim3(4, N / 128), 256, SMEM_GEMM>>>(agg, wst, b3, out, H * 128, 512, 0);
}

// round 7
// speedup vs baseline: 2.7799x; 1.0944x over previous
#include <cuda_runtime.h>
#include <cuda_fp16.h>
#include <cstdint>

constexpr int N    = 32768;
constexpr int EPER = 16384;
constexpr int T    = 8;
constexpr int E0   = T * EPER;   // 131072 typed edges
constexpr int E    = E0 + N;     // + self loops = 163840
constexpr int H    = 4;
constexpr float NEG = 0.2f;

// ---------------------------- scratch (device globals) ---------------------
__device__ float g_agg[(size_t)N * 512];    // L1: fp32 [N,H*K]; L2/L3: half (aliased)
__device__ float g_hbuf[(size_t)N * 128];   // inter-layer activations (fp32)
__device__ float g_ssrc[N * H];
__device__ float g_sdst[N * H];
__device__ float g_etab[(T + 1) * H];
__device__ float g_usrc[H * 128];
__device__ float g_udst[H * 128];
__device__ float g_wstack[512 * 512];       // L1: fp32 [H*K,dout]; L2/L3: half [dout,H*K] (aliased)
__device__ int   g_se[E];                   // dst-sorted packed edges: src | (et<<20)
__device__ int   g_src[E], g_dst[E], g_et[E];
__device__ int   g_deg[N], g_rowptr[N + 1], g_fill[N];

// ---------------------------- graph build (CSR by dst) ---------------------
__global__ void k_zero_deg() {
    int i = blockIdx.x * blockDim.x + threadIdx.x;
    if (i < N) g_deg[i] = 0;
}

__global__ void k_build(const int* __restrict__ eit) {
    int e = blockIdx.x * blockDim.x + threadIdx.x;
    if (e >= E) return;
    int s, d, t;
    if (e < E0) {
        t = e / EPER;
        int i = e - t * EPER;
        s = eit[t * 2 * EPER + i];
        d = eit[t * 2 * EPER + EPER + i];
    } else {
        s = d = e - E0;
        t = T;
    }
    g_src[e] = s; g_dst[e] = d; g_et[e] = t;
    atomicAdd(&g_deg[d], 1);
}

__global__ void k_scan() {
    __shared__ int sh[1024];
    int t = threadIdx.x;
    int base = t * 32;
    int loc[32];
    int sum = 0;
#pragma unroll
    for (int i = 0; i < 32; i++) { loc[i] = sum; sum += g_deg[base + i]; }
    sh[t] = sum;
    __syncthreads();
    for (int off = 1; off < 1024; off <<= 1) {
        int v = (t >= off) ? sh[t - off] : 0;
        __syncthreads();
        if (t >= off) sh[t] += v;
        __syncthreads();
    }
    int prev = (t == 0) ? 0 : sh[t - 1];
#pragma unroll
    for (int i = 0; i < 32; i++) {
        int v = prev + loc[i];
        g_rowptr[base + i] = v;
        g_fill[base + i]   = v;
    }
    if (t == 1023) g_rowptr[N] = sh[1023];
}

__global__ void k_scatter() {
    int e = blockIdx.x * blockDim.x + threadIdx.x;
    if (e >= E) return;
    int pos = atomicAdd(&g_fill[g_dst[e]], 1);
    g_se[pos] = g_src[e] | (g_et[e] << 20);
}

// ------------- fused per-layer prep: wstack + U vectors + edge table -------
// cvt=1: wstack written as HALF, transposed K-major: wst_h[d, h*K+k]
__global__ void k_prep(const float* __restrict__ W, const float* __restrict__ asrc,
                       const float* __restrict__ adst, const float* __restrict__ We,
                       const float* __restrict__ ae, int K, int dout, int wblocks,
                       int cvt) {
    __shared__ float sh[T][H];
    int b = blockIdx.x, tid = threadIdx.x;
    if (b < wblocks) {
        int idx = b * 256 + tid;
        if (idx < H * K * dout) {
            if (cvt) {
                int hk = idx % (H * K), d = idx / (H * K);
                int h = hk / K, k = hk % K;
                __half* wh = reinterpret_cast<__half*>(g_wstack);
                wh[(size_t)d * (H * K) + hk] =
                    __float2half(W[(size_t)k * (H * dout) + h * dout + d] * 0.25f);
            } else {
                int d = idx % dout;
                int hk = idx / dout;
                int h = hk / K, k = hk % K;
                g_wstack[idx] = W[(size_t)k * (H * dout) + h * dout + d] * 0.25f;
            }
        }
    } else if (b == wblocks) {
        for (int idx = tid; idx < H * K; idx += 256) {
            int h = idx / K, k = idx % K;
            const float* wr = W + (size_t)k * (H * dout) + h * dout;
            const float* as = asrc + h * dout;
            const float* ad = adst + h * dout;
            float vs = 0.f, vd = 0.f;
            for (int d = 0; d < dout; d++) { vs += wr[d] * as[d]; vd += wr[d] * ad[d]; }
            g_usrc[idx] = vs;
            g_udst[idx] = vd;
        }
    } else {
        int HC = H * dout;
        if (tid < T * H) {
            int t = tid >> 2, h = tid & 3;
            float s = 0.f;
            for (int c = 0; c < dout; c++) s += We[t * HC + h * dout + c] * ae[h * dout + c];
            sh[t][h] = s;
            g_etab[t * H + h] = s;
        }
        __syncthreads();
        if (tid < H) {
            float s = 0.f;
            for (int t = 0; t < T; t++) s += sh[t][tid];
            g_etab[T * H + tid] = s * (1.0f / T);
        }
    }
}

// ---------------------------- per-node attention scores --------------------
__global__ void k_scores(const float* __restrict__ h, int K) {
    int gw = (blockIdx.x * blockDim.x + threadIdx.x) >> 5;
    int lane = threadIdx.x & 31;
    if (gw >= N) return;
    const float* row = h + (size_t)gw * K;
    float acc[2][H];
#pragma unroll
    for (int i = 0; i < 2; i++)
#pragma unroll
        for (int hh = 0; hh < H; hh++) acc[i][hh] = 0.f;
    for (int k = lane; k < K; k += 32) {
        float x = row[k];
#pragma unroll
        for (int hh = 0; hh < H; hh++) {
            acc[0][hh] += x * g_usrc[hh * K + k];
            acc[1][hh] += x * g_udst[hh * K + k];
        }
    }
#pragma unroll
    for (int i = 0; i < 2; i++)
#pragma unroll
        for (int hh = 0; hh < H; hh++)
#pragma unroll
            for (int o = 16; o > 0; o >>= 1)
                acc[i][hh] += __shfl_xor_sync(0xffffffffu, acc[i][hh], o);
    if (lane < H)      g_ssrc[gw * H + lane] = acc[0][lane];
    else if (lane < 2 * H) g_sdst[gw * H + (lane - H)] = acc[1][lane - H];
}

// ------- fused alpha + online softmax + aggregation ------------------------
// CVT: write half output (for fp16 tensor-core GEMM)
template <int K, bool CVT>
__global__ void k_gat_edge(const float* __restrict__ h, float* __restrict__ aggf) {
    constexpr int CH = 32;
    constexpr bool BN = (K == 128);          // block-per-node
    __shared__ float s_w[BN ? 1 : 4][CH][H];
    __shared__ int   s_pk[BN ? 1 : 4][CH];

    int grp  = BN ? 0 : (threadIdx.x >> 5);
    int gtid = BN ? threadIdx.x : (threadIdx.x & 31);
    int n    = BN ? blockIdx.x : (blockIdx.x * 4 + grp);
    int b0 = g_rowptr[n], b1 = g_rowptr[n + 1];

    float m = -1e30f, s = 0.f;
    if (gtid < H) {
        float sd = g_sdst[n * H + gtid];
        for (int j = b0; j < b1; j++) {
            int p = g_se[j];
            int src = p & 0xFFFFF, et = p >> 20;
            float a = g_ssrc[src * H + gtid] + sd + g_etab[et * H + gtid];
            a = (a > 0.f) ? a : NEG * a;
            float mn = fmaxf(m, a);
            s = s * __expf(m - mn) + __expf(a - mn);
            m = mn;
        }
        s = 1.f / s;
    }

    float a0 = 0.f, a1 = 0.f, a2 = 0.f, a3 = 0.f;
    for (int j0 = b0; j0 < b1; j0 += CH) {
        int cnt = min(CH, b1 - j0);
        if (gtid < cnt) s_pk[grp][gtid] = g_se[j0 + gtid];
        if (BN) __syncthreads(); else __syncwarp();
        if (gtid < H) {
            float sd = g_sdst[n * H + gtid];
            for (int jj = 0; jj < cnt; jj++) {
                int p = s_pk[grp][jj];
                int src = p & 0xFFFFF, et = p >> 20;
                float a = g_ssrc[src * H + gtid] + sd + g_etab[et * H + gtid];
                a = (a > 0.f) ? a : NEG * a;
                s_w[grp][jj][gtid] = __expf(a - m) * s;
            }
        }
        if (BN) __syncthreads(); else __syncwarp();
        if (gtid < K) {
            for (int jj = 0; jj < cnt; jj++) {
                int src = s_pk[grp][jj] & 0xFFFFF;
                float v = h[(size_t)src * K + gtid];
                a0 += s_w[grp][jj][0] * v;
                a1 += s_w[grp][jj][1] * v;
                a2 += s_w[grp][jj][2] * v;
                a3 += s_w[grp][jj][3] * v;
            }
        }
        if (BN) __syncthreads(); else __syncwarp();
    }

    if (gtid < K) {
        size_t base = (size_t)n * (H * K) + gtid;
        if (CVT) {
            __half* ah = reinterpret_cast<__half*>(aggf);
            ah[base]         = __float2half(a0);
            ah[base + K]     = __float2half(a1);
            ah[base + 2 * K] = __float2half(a2);
            ah[base + 3 * K] = __float2half(a3);
        } else {
            aggf[base]         = a0;
            aggf[base + K]     = a1;
            aggf[base + 2 * K] = a2;
            aggf[base + 3 * K] = a3;
        }
    }
}

// ------------- small GEMM (layer 1): C = A[N,K] @ B[K,NN] + bias -----------
__global__ void k_gemm_small(const float* __restrict__ A, const float* __restrict__ B,
                             const float* __restrict__ bias, float* __restrict__ C,
                             int K, int NN, int relu) {
    int idx = blockIdx.x * blockDim.x + threadIdx.x;
    int n = idx / NN, d = idx % NN;
    if (n >= N) return;
    const float* ar = A + (size_t)n * K;
    float acc = 0.f;
    for (int k = 0; k < K; k++) acc += ar[k] * B[k * NN + d];
    acc += bias[d];
    if (relu) acc = fmaxf(acc, 0.f);
    C[(size_t)n * NN + d] = acc;
}

// ------- fp16 TC GEMM: C[m,d] = sum_k A[m,k]*Bt[d,k], 128x128x32 tiles -----
// A [M,K] half row-major; Bt [NN,K] half row-major. cp.async double buffer.
// Smem rows of 40 halves (80B stride) -> ldmatrix conflict-free.
constexpr int SMEM_HF = 4 * 128 * 40 * 2;   // 40960 B (2 bufs x (A+B) tiles)

__device__ __forceinline__ uint32_t smem_u32(const void* p) {
    uint32_t a;
    asm("{ .reg .u64 t; cvta.to.shared.u64 t, %1; cvt.u32.u64 %0, t; }" : "=r"(a) : "l"(p));
    return a;
}

__global__ void __launch_bounds__(256, 2)
k_gemm_hf(const __half* __restrict__ A, const __half* __restrict__ Bt,
          const float* __restrict__ bias, float* __restrict__ C,
          int K, int NN, int relu) {
    extern __shared__ char hsm[];
    __half (*As)[128][40] = reinterpret_cast<__half (*)[128][40]>(hsm);
    __half (*Bs)[128][40] = reinterpret_cast<__half (*)[128][40]>(hsm + 2 * 128 * 40 * 2);
    int tid = threadIdx.x;
    int wid = tid >> 5, lane = tid & 31;
    int bm = blockIdx.y * 128, bn = blockIdx.x * 128;
    int wm = (wid >> 2) * 64;
    int wn = (wid & 3) * 32;
    int grp = lane >> 2, tig = lane & 3;

    float c[4][4][4];
#pragma unroll
    for (int mt = 0; mt < 4; mt++)
#pragma unroll
        for (int nt = 0; nt < 4; nt++)
#pragma unroll
            for (int q = 0; q < 4; q++) c[mt][nt][q] = 0.f;

    int nk = K >> 5;

    auto copy_tile = [&](int s, int k0) {
#pragma unroll
        for (int i = 0; i < 2; i++) {
            int f = tid + i * 256;            // 512 chunks of 16B for A
            int m = f >> 2, q = f & 3;
            uint32_t dst = smem_u32(&As[s][m][q * 8]);
            const __half* src = &A[(size_t)(bm + m) * K + k0 + q * 8];
            asm volatile("cp.async.ca.shared.global [%0], [%1], 16;" :: "r"(dst), "l"(src));
        }
#pragma unroll
        for (int i = 0; i < 2; i++) {
            int f = tid + i * 256;            // 512 chunks of 16B for B
            int nrow = f >> 2, q = f & 3;
            uint32_t dst = smem_u32(&Bs[s][nrow][q * 8]);
            const __half* src = &Bt[(size_t)(bn + nrow) * K + k0 + q * 8];
            asm volatile("cp.async.ca.shared.global [%0], [%1], 16;" :: "r"(dst), "l"(src));
        }
        asm volatile("cp.async.commit_group;");
    };

    copy_tile(0, 0);

    int mtx = lane >> 3;          // 0..3: which 8x8 matrix this lane addresses
    int rin = lane & 7;

    for (int it = 0; it < nk; it++) {
        int cur = it & 1;
        if (it + 1 < nk) {
            copy_tile(cur ^ 1, (it + 1) * 32);
            asm volatile("cp.async.wait_group 1;");
        } else {
            asm volatile("cp.async.wait_group 0;");
        }
        __syncthreads();
#pragma unroll
        for (int ks = 0; ks < 2; ks++) {
            uint32_t a[4][4], b[4][2];
#pragma unroll
            for (int mt = 0; mt < 4; mt++) {
                // matrices: 0=(mLo,kLo) 1=(mHi,kLo) 2=(mLo,kHi) 3=(mHi,kHi)
                int row = wm + mt * 16 + (mtx & 1) * 8 + rin;
                int col = ks * 16 + (mtx >> 1) * 8;
                uint32_t addr = smem_u32(&As[cur][row][col]);
                asm volatile("ldmatrix.sync.aligned.m8n8.x4.shared.b16 {%0,%1,%2,%3}, [%4];"
                             : "=r"(a[mt][0]), "=r"(a[mt][1]), "=r"(a[mt][2]), "=r"(a[mt][3])
                             : "r"(addr));
            }
#pragma unroll
            for (int np = 0; np < 2; np++) {
                // matrices: 0=(nt0,kLo) 1=(nt0,kHi) 2=(nt1,kLo) 3=(nt1,kHi)
                int row = wn + np * 16 + (mtx >> 1) * 8 + rin;
                int col = ks * 16 + (mtx & 1) * 8;
                uint32_t addr = smem_u32(&Bs[cur][row][col]);
                asm volatile("ldmatrix.sync.aligned.m8n8.x4.shared.b16 {%0,%1,%2,%3}, [%4];"
                             : "=r"(b[np * 2][0]), "=r"(b[np * 2][1]),
                               "=r"(b[np * 2 + 1][0]), "=r"(b[np * 2 + 1][1])
                             : "r"(addr));
            }
#pragma unroll
            for (int mt = 0; mt < 4; mt++)
#pragma unroll
                for (int nt = 0; nt < 4; nt++) {
                    asm volatile(
                        "mma.sync.aligned.m16n8k16.row.col.f32.f16.f16.f32 "
                        "{%0,%1,%2,%3}, {%4,%5,%6,%7}, {%8,%9}, {%0,%1,%2,%3};"
                        : "+f"(c[mt][nt][0]), "+f"(c[mt][nt][1]),
                          "+f"(c[mt][nt][2]), "+f"(c[mt][nt][3])
                        : "r"(a[mt][0]), "r"(a[mt][1]), "r"(a[mt][2]), "r"(a[mt][3]),
                          "r"(b[nt][0]), "r"(b[nt][1]));
                }
        }
        __syncthreads();
    }

    // epilogue: bias (+relu); c layout: c0={g,2t} c1={g,2t+1} c2={g+8,2t} c3={g+8,2t+1}
#pragma unroll
    for (int mt = 0; mt < 4; mt++) {
#pragma unroll
        for (int nt = 0; nt < 4; nt++) {
            int col = bn + wn + nt * 8 + tig * 2;
            float bv0 = bias[col], bv1 = bias[col + 1];
            int r0 = bm + wm + mt * 16 + grp;
            float v00 = c[mt][nt][0] + bv0, v01 = c[mt][nt][1] + bv1;
            float v10 = c[mt][nt][2] + bv0, v11 = c[mt][nt][3] + bv1;
            if (relu) {
                v00 = fmaxf(v00, 0.f); v01 = fmaxf(v01, 0.f);
                v10 = fmaxf(v10, 0.f); v11 = fmaxf(v11, 0.f);
            }
            C[(size_t)r0 * NN + col]           = v00;
            C[(size_t)r0 * NN + col + 1]       = v01;
            C[(size_t)(r0 + 8) * NN + col]     = v10;
            C[(size_t)(r0 + 8) * NN + col + 1] = v11;
        }
    }
}

// ---------------------------------------------------------------------------
extern "C" void kernel_launch(void* const* d_in, const int* in_sizes, int n_in,
                              void* d_out, int out_size) {
    const float* x   = (const float*)d_in[0];
    const int*   eit = (const int*)d_in[1];
    const float* W1  = (const float*)d_in[2];
    const float* We1 = (const float*)d_in[3];
    const float* as1 = (const float*)d_in[4];
    const float* ad1 = (const float*)d_in[5];
    const float* ae1 = (const float*)d_in[6];
    const float* b1  = (const float*)d_in[7];
    const float* W2  = (const float*)d_in[8];
    const float* We2 = (const float*)d_in[9];
    const float* as2 = (const float*)d_in[10];
    const float* ad2 = (const float*)d_in[11];
    const float* ae2 = (const float*)d_in[12];
    const float* b2  = (const float*)d_in[13];
    const float* W3  = (const float*)d_in[14];
    const float* We3 = (const float*)d_in[15];
    const float* as3 = (const float*)d_in[16];
    const float* ad3 = (const float*)d_in[17];
    const float* ae3 = (const float*)d_in[18];
    const float* b3  = (const float*)d_in[19];
    float* out = (float*)d_out;

    float *agg = nullptr, *hbuf = nullptr, *wst = nullptr;
    cudaGetSymbolAddress((void**)&agg, g_agg);
    cudaGetSymbolAddress((void**)&hbuf, g_hbuf);
    cudaGetSymbolAddress((void**)&wst, g_wstack);
    const __half* aggh = (const __half*)agg;
    const __half* wsth = (const __half*)wst;

    cudaFuncSetAttribute(k_gemm_hf, cudaFuncAttributeMaxDynamicSharedMemorySize, SMEM_HF);

    // ---- graph build (CSR by dst, packed sorted edges) ----
    k_zero_deg<<<N / 256, 256>>>();
    k_build<<<E / 256, 256>>>(eit);
    k_scan<<<1, 1024>>>();
    k_scatter<<<E / 256, 256>>>();

    // ---- layer 1: K=16 -> dout=32 (fp32 SIMT path) ----
    {
        int wb = (H * 16 * 32 + 255) / 256;
        k_prep<<<wb + 2, 256>>>(W1, as1, ad1, We1, ae1, 16, 32, wb, 0);
    }
    k_scores<<<N / 8, 256>>>(x, 16);
    k_gat_edge<16, false><<<N / 4, 128>>>(x, agg);
    k_gemm_small<<<(N * 32) / 256, 256>>>(agg, wst, b1, hbuf, H * 16, 32, 1);

    // ---- layer 2: K=32 -> dout=128 (fp16 TC GEMM) ----
    {
        int wb = (H * 32 * 128 + 255) / 256;
        k_prep<<<wb + 2, 256>>>(W2, as2, ad2, We2, ae2, 32, 128, wb, 1);
    }
    k_scores<<<N / 8, 256>>>(hbuf, 32);
    k_gat_edge<32, true><<<N / 4, 128>>>(hbuf, agg);
    k_gemm_hf<<<dim3(1, N / 128), 256, SMEM_HF>>>(aggh, wsth, b2, hbuf, H * 32, 128, 1);

    // ---- layer 3: K=128 -> dout=512 (fp16 TC GEMM, writes d_out) ----
    {
        int wb = (H * 128 * 512 + 255) / 256;
        k_prep<<<wb + 2, 256>>>(W3, as3, ad3, We3, ae3, 128, 512, wb, 1);
    }
    k_scores<<<N / 8, 256>>>(hbuf, 128);
    k_gat_edge<128, true><<<N, 128>>>(hbuf, agg);
    k_gemm_hf<<<dim3(4, N / 128), 256, SMEM_HF>>>(aggh, wsth, b3, out, H * 128, 512, 0);
}

// round 8
// speedup vs baseline: 2.9489x; 1.0608x over previous
#include <cuda_runtime.h>
#include <cuda_fp16.h>
#include <cstdint>

constexpr int N    = 32768;
constexpr int EPER = 16384;
constexpr int T    = 8;
constexpr int E0   = T * EPER;   // 131072 typed edges
constexpr int E    = E0 + N;     // + self loops = 163840
constexpr int H    = 4;
constexpr float NEG = 0.2f;

// ---------------------------- scratch (device globals) ---------------------
__device__ float g_agg[(size_t)N * 512];    // L1: fp32 [N,H*K]; L2/L3: half (aliased)
__device__ float g_hbuf[(size_t)N * 128];   // inter-layer activations (fp32)
__device__ float g_ssrc[N * H];
__device__ float g_sdst[N * H];
__device__ float g_etab[(T + 1) * H];
__device__ float g_usrc[H * 128];
__device__ float g_udst[H * 128];
__device__ float g_wstack[512 * 512];       // L1: fp32 [H*K,dout]; L2/L3: half [dout,H*K] (aliased)
__device__ int   g_se[E];                   // dst-sorted packed edges: src | (et<<20)
__device__ int   g_src[E], g_dst[E], g_et[E];
__device__ int   g_deg[N], g_rowptr[N + 1], g_fill[N];

// ---------------------------- graph build (CSR by dst) ---------------------
__global__ void k_zero_deg() {
    int i = blockIdx.x * blockDim.x + threadIdx.x;
    if (i < N) g_deg[i] = 0;
}

__global__ void k_build(const int* __restrict__ eit) {
    int e = blockIdx.x * blockDim.x + threadIdx.x;
    if (e >= E) return;
    int s, d, t;
    if (e < E0) {
        t = e / EPER;
        int i = e - t * EPER;
        s = eit[t * 2 * EPER + i];
        d = eit[t * 2 * EPER + EPER + i];
    } else {
        s = d = e - E0;
        t = T;
    }
    g_src[e] = s; g_dst[e] = d; g_et[e] = t;
    atomicAdd(&g_deg[d], 1);
}

__global__ void k_scan() {
    __shared__ int sh[1024];
    int t = threadIdx.x;
    int base = t * 32;
    int loc[32];
    int sum = 0;
#pragma unroll
    for (int i = 0; i < 32; i++) { loc[i] = sum; sum += g_deg[base + i]; }
    sh[t] = sum;
    __syncthreads();
    for (int off = 1; off < 1024; off <<= 1) {
        int v = (t >= off) ? sh[t - off] : 0;
        __syncthreads();
        if (t >= off) sh[t] += v;
        __syncthreads();
    }
    int prev = (t == 0) ? 0 : sh[t - 1];
#pragma unroll
    for (int i = 0; i < 32; i++) {
        int v = prev + loc[i];
        g_rowptr[base + i] = v;
        g_fill[base + i]   = v;
    }
    if (t == 1023) g_rowptr[N] = sh[1023];
}

__global__ void k_scatter() {
    int e = blockIdx.x * blockDim.x + threadIdx.x;
    if (e >= E) return;
    int pos = atomicAdd(&g_fill[g_dst[e]], 1);
    g_se[pos] = g_src[e] | (g_et[e] << 20);
}

// ------------- fused per-layer prep: wstack + U vectors + edge table -------
__global__ void k_prep(const float* __restrict__ W, const float* __restrict__ asrc,
                       const float* __restrict__ adst, const float* __restrict__ We,
                       const float* __restrict__ ae, int K, int dout, int wblocks,
                       int cvt) {
    __shared__ float sh[T][H];
    int b = blockIdx.x, tid = threadIdx.x;
    if (b < wblocks) {
        int idx = b * 256 + tid;
        if (idx < H * K * dout) {
            if (cvt) {
                int hk = idx % (H * K), d = idx / (H * K);
                int h = hk / K, k = hk % K;
                __half* wh = reinterpret_cast<__half*>(g_wstack);
                wh[(size_t)d * (H * K) + hk] =
                    __float2half(W[(size_t)k * (H * dout) + h * dout + d] * 0.25f);
            } else {
                int d = idx % dout;
                int hk = idx / dout;
                int h = hk / K, k = hk % K;
                g_wstack[idx] = W[(size_t)k * (H * dout) + h * dout + d] * 0.25f;
            }
        }
    } else if (b == wblocks) {
        for (int idx = tid; idx < H * K; idx += 256) {
            int h = idx / K, k = idx % K;
            const float* wr = W + (size_t)k * (H * dout) + h * dout;
            const float* as = asrc + h * dout;
            const float* ad = adst + h * dout;
            float vs = 0.f, vd = 0.f;
            for (int d = 0; d < dout; d++) { vs += wr[d] * as[d]; vd += wr[d] * ad[d]; }
            g_usrc[idx] = vs;
            g_udst[idx] = vd;
        }
    } else {
        int HC = H * dout;
        if (tid < T * H) {
            int t = tid >> 2, h = tid & 3;
            float s = 0.f;
            for (int c = 0; c < dout; c++) s += We[t * HC + h * dout + c] * ae[h * dout + c];
            sh[t][h] = s;
            g_etab[t * H + h] = s;
        }
        __syncthreads();
        if (tid < H) {
            float s = 0.f;
            for (int t = 0; t < T; t++) s += sh[t][tid];
            g_etab[T * H + tid] = s * (1.0f / T);
        }
    }
}

// ---------------------------- per-node attention scores --------------------
__global__ void k_scores(const float* __restrict__ h, int K) {
    int gw = (blockIdx.x * blockDim.x + threadIdx.x) >> 5;
    int lane = threadIdx.x & 31;
    if (gw >= N) return;
    const float* row = h + (size_t)gw * K;
    float acc[2][H];
#pragma unroll
    for (int i = 0; i < 2; i++)
#pragma unroll
        for (int hh = 0; hh < H; hh++) acc[i][hh] = 0.f;
    for (int k = lane; k < K; k += 32) {
        float x = row[k];
#pragma unroll
        for (int hh = 0; hh < H; hh++) {
            acc[0][hh] += x * g_usrc[hh * K + k];
            acc[1][hh] += x * g_udst[hh * K + k];
        }
    }
#pragma unroll
    for (int i = 0; i < 2; i++)
#pragma unroll
        for (int hh = 0; hh < H; hh++)
#pragma unroll
            for (int o = 16; o > 0; o >>= 1)
                acc[i][hh] += __shfl_xor_sync(0xffffffffu, acc[i][hh], o);
    if (lane < H)      g_ssrc[gw * H + lane] = acc[0][lane];
    else if (lane < 2 * H) g_sdst[gw * H + (lane - H)] = acc[1][lane - H];
}

// ------- fused alpha + softmax + aggregation (warp-parallel softmax) -------
// K==128: one node per 128-thread block. K<=32: one node per warp (4/block).
// Alphas computed ONCE by a full warp over (edge,head) pairs; butterfly
// logsumexp merge; smem weights; then aggregation. Fallback path for deg>CAP.
template <int K, bool CVT>
__global__ void k_gat_edge(const float* __restrict__ h, float* __restrict__ aggf) {
    constexpr int CAP = 128;
    constexpr bool BN = (K == 128);
    constexpr int NG = BN ? 1 : 4;
    __shared__ int   s_pk[NG][CAP];
    __shared__ float s_aw[NG][CAP][H];

    int lane = threadIdx.x & 31;
    int wid  = threadIdx.x >> 5;
    int grp  = BN ? 0 : wid;
    int gtid = BN ? threadIdx.x : lane;
    int n    = BN ? blockIdx.x : (blockIdx.x * 4 + grp);
    int b0 = g_rowptr[n], b1 = g_rowptr[n + 1];
    int D = b1 - b0;

    float a0 = 0.f, a1 = 0.f, a2 = 0.f, a3 = 0.f;

    if (D <= CAP) {
        // ---- load edge list ----
        for (int j = gtid; j < D; j += (BN ? 128 : 32)) s_pk[grp][j] = g_se[b0 + j];
        if (BN) __syncthreads(); else __syncwarp();

        // ---- warp-parallel alpha + online (m,s) ----
        if (!BN || wid == 0) {
            int hh = lane & 3;
            int j0 = lane >> 2;
            float sd = g_sdst[n * H + hh];
            float m = -1e30f, s = 0.f;
            for (int jj = j0; jj < D; jj += 8) {
                int p = s_pk[grp][jj];
                int src = p & 0xFFFFF, et = p >> 20;
                float a = g_ssrc[src * H + hh] + sd + g_etab[et * H + hh];
                a = (a > 0.f) ? a : NEG * a;
                s_aw[grp][jj][hh] = a;
                float mn = fmaxf(m, a);
                s = s * __expf(m - mn) + __expf(a - mn);
                m = mn;
            }
            // butterfly logsumexp merge within head class (xor 4,8,16)
#pragma unroll
            for (int o = 4; o <= 16; o <<= 1) {
                float m2 = __shfl_xor_sync(0xffffffffu, m, o);
                float s2 = __shfl_xor_sync(0xffffffffu, s, o);
                float mn = fmaxf(m, m2);
                s = s * __expf(m - mn) + s2 * __expf(m2 - mn);
                m = mn;
            }
            float inv = 1.f / s;
            for (int jj = j0; jj < D; jj += 8)
                s_aw[grp][jj][hh] = __expf(s_aw[grp][jj][hh] - m) * inv;
        }
        if (BN) __syncthreads(); else __syncwarp();

        // ---- aggregation ----
        if (gtid < K) {
            for (int jj = 0; jj < D; jj++) {
                int src = s_pk[grp][jj] & 0xFFFFF;
                float v = h[(size_t)src * K + gtid];
                a0 += s_aw[grp][jj][0] * v;
                a1 += s_aw[grp][jj][1] * v;
                a2 += s_aw[grp][jj][2] * v;
                a3 += s_aw[grp][jj][3] * v;
            }
        }
    } else {
        // ---- fallback (deg > CAP): serial online softmax + chunked recompute ----
        float m = -1e30f, s = 0.f;
        if (gtid < H) {
            float sd = g_sdst[n * H + gtid];
            for (int j = b0; j < b1; j++) {
                int p = g_se[j];
                int src = p & 0xFFFFF, et = p >> 20;
                float a = g_ssrc[src * H + gtid] + sd + g_etab[et * H + gtid];
                a = (a > 0.f) ? a : NEG * a;
                float mn = fmaxf(m, a);
                s = s * __expf(m - mn) + __expf(a - mn);
                m = mn;
            }
            s = 1.f / s;
        }
        for (int j0 = b0; j0 < b1; j0 += CAP) {
            int cnt = min(CAP, b1 - j0);
            for (int j = gtid; j < cnt; j += (BN ? 128 : 32)) s_pk[grp][j] = g_se[j0 + j];
            if (BN) __syncthreads(); else __syncwarp();
            if (gtid < H) {
                float sd = g_sdst[n * H + gtid];
                for (int jj = 0; jj < cnt; jj++) {
                    int p = s_pk[grp][jj];
                    int src = p & 0xFFFFF, et = p >> 20;
                    float a = g_ssrc[src * H + gtid] + sd + g_etab[et * H + gtid];
                    a = (a > 0.f) ? a : NEG * a;
                    s_aw[grp][jj][gtid] = __expf(a - m) * s;
                }
            }
            if (BN) __syncthreads(); else __syncwarp();
            if (gtid < K) {
                for (int jj = 0; jj < cnt; jj++) {
                    int src = s_pk[grp][jj] & 0xFFFFF;
                    float v = h[(size_t)src * K + gtid];
                    a0 += s_aw[grp][jj][0] * v;
                    a1 += s_aw[grp][jj][1] * v;
                    a2 += s_aw[grp][jj][2] * v;
                    a3 += s_aw[grp][jj][3] * v;
                }
            }
            if (BN) __syncthreads(); else __syncwarp();
        }
    }

    if (gtid < K) {
        size_t base = (size_t)n * (H * K) + gtid;
        if (CVT) {
            __half* ah = reinterpret_cast<__half*>(aggf);
            ah[base]         = __float2half(a0);
            ah[base + K]     = __float2half(a1);
            ah[base + 2 * K] = __float2half(a2);
            ah[base + 3 * K] = __float2half(a3);
        } else {
            aggf[base]         = a0;
            aggf[base + K]     = a1;
            aggf[base + 2 * K] = a2;
            aggf[base + 3 * K] = a3;
        }
    }
}

// ------------- small GEMM (layer 1): C = A[N,K] @ B[K,NN] + bias -----------
__global__ void k_gemm_small(const float* __restrict__ A, const float* __restrict__ B,
                             const float* __restrict__ bias, float* __restrict__ C,
                             int K, int NN, int relu) {
    int idx = blockIdx.x * blockDim.x + threadIdx.x;
    int n = idx / NN, d = idx % NN;
    if (n >= N) return;
    const float* ar = A + (size_t)n * K;
    float acc = 0.f;
    for (int k = 0; k < K; k++) acc += ar[k] * B[k * NN + d];
    acc += bias[d];
    if (relu) acc = fmaxf(acc, 0.f);
    C[(size_t)n * NN + d] = acc;
}

// ------- fp16 TC GEMM: C[m,d] = sum_k A[m,k]*Bt[d,k], 128x128x32 tiles -----
constexpr int SMEM_HF = 4 * 128 * 40 * 2;   // 40960 B

__device__ __forceinline__ uint32_t smem_u32(const void* p) {
    uint32_t a;
    asm("{ .reg .u64 t; cvta.to.shared.u64 t, %1; cvt.u32.u64 %0, t; }" : "=r"(a) : "l"(p));
    return a;
}

__global__ void __launch_bounds__(256, 2)
k_gemm_hf(const __half* __restrict__ A, const __half* __restrict__ Bt,
          const float* __restrict__ bias, float* __restrict__ C,
          int K, int NN, int relu) {
    extern __shared__ char hsm[];
    __half (*As)[128][40] = reinterpret_cast<__half (*)[128][40]>(hsm);
    __half (*Bs)[128][40] = reinterpret_cast<__half (*)[128][40]>(hsm + 2 * 128 * 40 * 2);
    int tid = threadIdx.x;
    int wid = tid >> 5, lane = tid & 31;
    int bm = blockIdx.y * 128, bn = blockIdx.x * 128;
    int wm = (wid >> 2) * 64;
    int wn = (wid & 3) * 32;
    int grp = lane >> 2, tig = lane & 3;

    float c[4][4][4];
#pragma unroll
    for (int mt = 0; mt < 4; mt++)
#pragma unroll
        for (int nt = 0; nt < 4; nt++)
#pragma unroll
            for (int q = 0; q < 4; q++) c[mt][nt][q] = 0.f;

    int nk = K >> 5;

    auto copy_tile = [&](int s, int k0) {
#pragma unroll
        for (int i = 0; i < 2; i++) {
            int f = tid + i * 256;
            int m = f >> 2, q = f & 3;
            uint32_t dst = smem_u32(&As[s][m][q * 8]);
            const __half* src = &A[(size_t)(bm + m) * K + k0 + q * 8];
            asm volatile("cp.async.ca.shared.global [%0], [%1], 16;" :: "r"(dst), "l"(src));
        }
#pragma unroll
        for (int i = 0; i < 2; i++) {
            int f = tid + i * 256;
            int nrow = f >> 2, q = f & 3;
            uint32_t dst = smem_u32(&Bs[s][nrow][q * 8]);
            const __half* src = &Bt[(size_t)(bn + nrow) * K + k0 + q * 8];
            asm volatile("cp.async.ca.shared.global [%0], [%1], 16;" :: "r"(dst), "l"(src));
        }
        asm volatile("cp.async.commit_group;");
    };

    copy_tile(0, 0);

    int mtx = lane >> 3;
    int rin = lane & 7;

    for (int it = 0; it < nk; it++) {
        int cur = it & 1;
        if (it + 1 < nk) {
            copy_tile(cur ^ 1, (it + 1) * 32);
            asm volatile("cp.async.wait_group 1;");
        } else {
            asm volatile("cp.async.wait_group 0;");
        }
        __syncthreads();
#pragma unroll
        for (int ks = 0; ks < 2; ks++) {
            uint32_t a[4][4], b[4][2];
#pragma unroll
            for (int mt = 0; mt < 4; mt++) {
                int row = wm + mt * 16 + (mtx & 1) * 8 + rin;
                int col = ks * 16 + (mtx >> 1) * 8;
                uint32_t addr = smem_u32(&As[cur][row][col]);
                asm volatile("ldmatrix.sync.aligned.m8n8.x4.shared.b16 {%0,%1,%2,%3}, [%4];"
                             : "=r"(a[mt][0]), "=r"(a[mt][1]), "=r"(a[mt][2]), "=r"(a[mt][3])
                             : "r"(addr));
            }
#pragma unroll
            for (int np = 0; np < 2; np++) {
                int row = wn + np * 16 + (mtx >> 1) * 8 + rin;
                int col = ks * 16 + (mtx & 1) * 8;
                uint32_t addr = smem_u32(&Bs[cur][row][col]);
                asm volatile("ldmatrix.sync.aligned.m8n8.x4.shared.b16 {%0,%1,%2,%3}, [%4];"
                             : "=r"(b[np * 2][0]), "=r"(b[np * 2][1]),
                               "=r"(b[np * 2 + 1][0]), "=r"(b[np * 2 + 1][1])
                             : "r"(addr));
            }
#pragma unroll
            for (int mt = 0; mt < 4; mt++)
#pragma unroll
                for (int nt = 0; nt < 4; nt++) {
                    asm volatile(
                        "mma.sync.aligned.m16n8k16.row.col.f32.f16.f16.f32 "
                        "{%0,%1,%2,%3}, {%4,%5,%6,%7}, {%8,%9}, {%0,%1,%2,%3};"
                        : "+f"(c[mt][nt][0]), "+f"(c[mt][nt][1]),
                          "+f"(c[mt][nt][2]), "+f"(c[mt][nt][3])
                        : "r"(a[mt][0]), "r"(a[mt][1]), "r"(a[mt][2]), "r"(a[mt][3]),
                          "r"(b[nt][0]), "r"(b[nt][1]));
                }
        }
        __syncthreads();
    }

#pragma unroll
    for (int mt = 0; mt < 4; mt++) {
#pragma unroll
        for (int nt = 0; nt < 4; nt++) {
            int col = bn + wn + nt * 8 + tig * 2;
            float bv0 = bias[col], bv1 = bias[col + 1];
            int r0 = bm + wm + mt * 16 + grp;
            float v00 = c[mt][nt][0] + bv0, v01 = c[mt][nt][1] + bv1;
            float v10 = c[mt][nt][2] + bv0, v11 = c[mt][nt][3] + bv1;
            if (relu) {
                v00 = fmaxf(v00, 0.f); v01 = fmaxf(v01, 0.f);
                v10 = fmaxf(v10, 0.f); v11 = fmaxf(v11, 0.f);
            }
            C[(size_t)r0 * NN + col]           = v00;
            C[(size_t)r0 * NN + col + 1]       = v01;
            C[(size_t)(r0 + 8) * NN + col]     = v10;
            C[(size_t)(r0 + 8) * NN + col + 1] = v11;
        }
    }
}

// ---------------------------------------------------------------------------
extern "C" void kernel_launch(void* const* d_in, const int* in_sizes, int n_in,
                              void* d_out, int out_size) {
    const float* x   = (const float*)d_in[0];
    const int*   eit = (const int*)d_in[1];
    const float* W1  = (const float*)d_in[2];
    const float* We1 = (const float*)d_in[3];
    const float* as1 = (const float*)d_in[4];
    const float* ad1 = (const float*)d_in[5];
    const float* ae1 = (const float*)d_in[6];
    const float* b1  = (const float*)d_in[7];
    const float* W2  = (const float*)d_in[8];
    const float* We2 = (const float*)d_in[9];
    const float* as2 = (const float*)d_in[10];
    const float* ad2 = (const float*)d_in[11];
    const float* ae2 = (const float*)d_in[12];
    const float* b2  = (const float*)d_in[13];
    const float* W3  = (const float*)d_in[14];
    const float* We3 = (const float*)d_in[15];
    const float* as3 = (const float*)d_in[16];
    const float* ad3 = (const float*)d_in[17];
    const float* ae3 = (const float*)d_in[18];
    const float* b3  = (const float*)d_in[19];
    float* out = (float*)d_out;

    float *agg = nullptr, *hbuf = nullptr, *wst = nullptr;
    cudaGetSymbolAddress((void**)&agg, g_agg);
    cudaGetSymbolAddress((void**)&hbuf, g_hbuf);
    cudaGetSymbolAddress((void**)&wst, g_wstack);
    const __half* aggh = (const __half*)agg;
    const __half* wsth = (const __half*)wst;

    cudaFuncSetAttribute(k_gemm_hf, cudaFuncAttributeMaxDynamicSharedMemorySize, SMEM_HF);

    // ---- graph build (CSR by dst, packed sorted edges) ----
    k_zero_deg<<<N / 256, 256>>>();
    k_build<<<E / 256, 256>>>(eit);
    k_scan<<<1, 1024>>>();
    k_scatter<<<E / 256, 256>>>();

    // ---- layer 1: K=16 -> dout=32 (fp32 SIMT path) ----
    {
        int wb = (H * 16 * 32 + 255) / 256;
        k_prep<<<wb + 2, 256>>>(W1, as1, ad1, We1, ae1, 16, 32, wb, 0);
    }
    k_scores<<<N / 8, 256>>>(x, 16);
    k_gat_edge<16, false><<<N / 4, 128>>>(x, agg);
    k_gemm_small<<<(N * 32) / 256, 256>>>(agg, wst, b1, hbuf, H * 16, 32, 1);

    // ---- layer 2: K=32 -> dout=128 (fp16 TC GEMM) ----
    {
        int wb = (H * 32 * 128 + 255) / 256;
        k_prep<<<wb + 2, 256>>>(W2, as2, ad2, We2, ae2, 32, 128, wb, 1);
    }
    k_scores<<<N / 8, 256>>>(hbuf, 32);
    k_gat_edge<32, true><<<N / 4, 128>>>(hbuf, agg);
    k_gemm_hf<<<dim3(1, N / 128), 256, SMEM_HF>>>(aggh, wsth, b2, hbuf, H * 32, 128, 1);

    // ---- layer 3: K=128 -> dout=512 (fp16 TC GEMM, writes d_out) ----
    {
        int wb = (H * 128 * 512 + 255) / 256;
        k_prep<<<wb + 2, 256>>>(W3, as3, ad3, We3, ae3, 128, 512, wb, 1);
    }
    k_scores<<<N / 8, 256>>>(hbuf, 128);
    k_gat_edge<128, true><<<N, 128>>>(hbuf, agg);
    k_gemm_hf<<<dim3(4, N / 128), 256, SMEM_HF>>>(aggh, wsth, b3, out, H * 128, 512, 0);
}

// round 9
// speedup vs baseline: 3.2280x; 1.0946x over previous
#include <cuda_runtime.h>
#include <cuda_fp16.h>
#include <cstdint>

constexpr int N    = 32768;
constexpr int EPER = 16384;
constexpr int T    = 8;
constexpr int E0   = T * EPER;   // 131072 typed edges
constexpr int E    = E0 + N;     // + self loops = 163840
constexpr int H    = 4;
constexpr float NEG = 0.2f;

// ---------------------------- scratch (device globals) ---------------------
__device__ float   g_agg[(size_t)N * 512];   // L1 fp32 [N,64]; L2/L3 half (aliased)
__device__ float   g_hbuf[(size_t)N * 128];  // inter-layer activations (fp32)
__device__ __half2 g_hbufh2[(size_t)N * 64]; // half mirror of hbuf for L3 gathers
__device__ float   g_ssrc[N * H];
__device__ float   g_sdst[N * H];
__device__ float   g_etab[3][(T + 1) * H];
__device__ float   g_usrc[3][512];
__device__ float   g_udst[3][512];
__device__ float   g_wst1[64 * 32];          // L1 fp32 [H*K, dout]
__device__ __half  g_wst2[128 * 128];        // L2 half [dout, H*K] K-major
__device__ __half  g_wst3[512 * 512];        // L3 half [dout, H*K] K-major
__device__ int     g_se[E];                  // dst-sorted packed edges: src | (et<<20)
__device__ int     g_src[E], g_dst[E], g_et[E];
__device__ int     g_deg[N], g_rowptr[N + 1], g_fill[N];

// ---------------------------- graph build (CSR by dst) ---------------------
__global__ void k_zero_deg() {
    int i = blockIdx.x * blockDim.x + threadIdx.x;
    if (i < N) g_deg[i] = 0;
}

__global__ void k_build(const int* __restrict__ eit) {
    int e = blockIdx.x * blockDim.x + threadIdx.x;
    if (e >= E) return;
    int s, d, t;
    if (e < E0) {
        t = e / EPER;
        int i = e - t * EPER;
        s = eit[t * 2 * EPER + i];
        d = eit[t * 2 * EPER + EPER + i];
    } else {
        s = d = e - E0;
        t = T;
    }
    g_src[e] = s; g_dst[e] = d; g_et[e] = t;
    atomicAdd(&g_deg[d], 1);
}

__global__ void k_scan() {
    __shared__ int sh[1024];
    int t = threadIdx.x;
    int base = t * 32;
    int loc[32];
    int sum = 0;
#pragma unroll
    for (int i = 0; i < 32; i++) { loc[i] = sum; sum += g_deg[base + i]; }
    sh[t] = sum;
    __syncthreads();
    for (int off = 1; off < 1024; off <<= 1) {
        int v = (t >= off) ? sh[t - off] : 0;
        __syncthreads();
        if (t >= off) sh[t] += v;
        __syncthreads();
    }
    int prev = (t == 0) ? 0 : sh[t - 1];
#pragma unroll
    for (int i = 0; i < 32; i++) {
        int v = prev + loc[i];
        g_rowptr[base + i] = v;
        g_fill[base + i]   = v;
    }
    if (t == 1023) g_rowptr[N] = sh[1023];
}

__global__ void k_scatter() {
    int e = blockIdx.x * blockDim.x + threadIdx.x;
    if (e >= E) return;
    int pos = atomicAdd(&g_fill[g_dst[e]], 1);
    g_se[pos] = g_src[e] | (g_et[e] << 20);
}

// ------------- ONE fused prep kernel for all three layers ------------------
// blocks [0,8): wst1   [8,72): wst2   [72,1096): wst3
// 1096+L: U vectors layer L    1099+L: edge table layer L
__global__ void k_prep_all(
    const float* __restrict__ W1, const float* __restrict__ as1,
    const float* __restrict__ ad1, const float* __restrict__ We1,
    const float* __restrict__ ae1,
    const float* __restrict__ W2, const float* __restrict__ as2,
    const float* __restrict__ ad2, const float* __restrict__ We2,
    const float* __restrict__ ae2,
    const float* __restrict__ W3, const float* __restrict__ as3,
    const float* __restrict__ ad3, const float* __restrict__ We3,
    const float* __restrict__ ae3) {
    __shared__ float sh[T][H];
    int b = blockIdx.x, tid = threadIdx.x;
    if (b < 8) {
        int idx = b * 256 + tid;                 // 2048 = 64*32
        int d = idx % 32, hk = idx / 32;
        int h = hk / 16, k = hk % 16;
        g_wst1[idx] = W1[(size_t)k * 128 + h * 32 + d] * 0.25f;
    } else if (b < 72) {
        int idx = (b - 8) * 256 + tid;           // 16384 = 128*128
        int hk = idx % 128, d = idx / 128;
        int h = hk / 32, k = hk % 32;
        g_wst2[(size_t)d * 128 + hk] = __float2half(W2[(size_t)k * 512 + h * 128 + d] * 0.25f);
    } else if (b < 1096) {
        int idx = (b - 72) * 256 + tid;          // 262144 = 512*512
        int hk = idx % 512, d = idx / 512;
        int h = hk / 128, k = hk % 128;
        g_wst3[(size_t)d * 512 + hk] = __float2half(W3[(size_t)k * 2048 + h * 512 + d] * 0.25f);
    } else if (b < 1099) {
        int L = b - 1096;
        int K = (L == 0) ? 16 : (L == 1) ? 32 : 128;
        int dout = (L == 0) ? 32 : (L == 1) ? 128 : 512;
        const float* W  = (L == 0) ? W1  : (L == 1) ? W2  : W3;
        const float* as = (L == 0) ? as1 : (L == 1) ? as2 : as3;
        const float* ad = (L == 0) ? ad1 : (L == 1) ? ad2 : ad3;
        for (int idx = tid; idx < H * K; idx += 256) {
            int h = idx / K, k = idx % K;
            const float* wr = W + (size_t)k * (H * dout) + h * dout;
            float vs = 0.f, vd = 0.f;
            for (int d = 0; d < dout; d++) {
                vs += wr[d] * as[h * dout + d];
                vd += wr[d] * ad[h * dout + d];
            }
            g_usrc[L][idx] = vs;
            g_udst[L][idx] = vd;
        }
    } else {
        int L = b - 1099;
        int dout = (L == 0) ? 32 : (L == 1) ? 128 : 512;
        const float* We = (L == 0) ? We1 : (L == 1) ? We2 : We3;
        const float* ae = (L == 0) ? ae1 : (L == 1) ? ae2 : ae3;
        int HC = H * dout;
        if (tid < T * H) {
            int t = tid >> 2, h = tid & 3;
            float s = 0.f;
            for (int c = 0; c < dout; c++) s += We[t * HC + h * dout + c] * ae[h * dout + c];
            sh[t][h] = s;
            g_etab[L][t * H + h] = s;
        }
        __syncthreads();
        if (tid < H) {
            float s = 0.f;
            for (int t = 0; t < T; t++) s += sh[t][tid];
            g_etab[L][T * H + tid] = s * (1.0f / T);
        }
    }
}

// ---------------------------- per-node attention scores --------------------
__global__ void k_scores(const float* __restrict__ h, int K, int L) {
    int gw = (blockIdx.x * blockDim.x + threadIdx.x) >> 5;
    int lane = threadIdx.x & 31;
    if (gw >= N) return;
    const float* row = h + (size_t)gw * K;
    float acc[2][H];
#pragma unroll
    for (int i = 0; i < 2; i++)
#pragma unroll
        for (int hh = 0; hh < H; hh++) acc[i][hh] = 0.f;
    for (int k = lane; k < K; k += 32) {
        float x = row[k];
#pragma unroll
        for (int hh = 0; hh < H; hh++) {
            acc[0][hh] += x * g_usrc[L][hh * K + k];
            acc[1][hh] += x * g_udst[L][hh * K + k];
        }
    }
#pragma unroll
    for (int i = 0; i < 2; i++)
#pragma unroll
        for (int hh = 0; hh < H; hh++)
#pragma unroll
            for (int o = 16; o > 0; o >>= 1)
                acc[i][hh] += __shfl_xor_sync(0xffffffffu, acc[i][hh], o);
    if (lane < H)      g_ssrc[gw * H + lane] = acc[0][lane];
    else if (lane < 2 * H) g_sdst[gw * H + (lane - H)] = acc[1][lane - H];
}

// ------- fused alpha + softmax + aggregation, K<=32 (warp per node) --------
template <int K, bool CVT>
__global__ void k_gat_edge(const float* __restrict__ h, float* __restrict__ aggf, int L) {
    constexpr int CAP = 128;
    __shared__ int   s_pk[4][CAP];
    __shared__ float s_aw[4][CAP][H];

    int lane = threadIdx.x & 31;
    int grp  = threadIdx.x >> 5;
    int n    = blockIdx.x * 4 + grp;
    int b0 = g_rowptr[n], b1 = g_rowptr[n + 1];
    int D = b1 - b0;

    float a0 = 0.f, a1 = 0.f, a2 = 0.f, a3 = 0.f;

    if (D <= CAP) {
        for (int j = lane; j < D; j += 32) s_pk[grp][j] = g_se[b0 + j];
        __syncwarp();
        {
            int hh = lane & 3;
            int j0 = lane >> 2;
            float sd = g_sdst[n * H + hh];
            float m = -1e30f, s = 0.f;
            for (int jj = j0; jj < D; jj += 8) {
                int p = s_pk[grp][jj];
                int src = p & 0xFFFFF, et = p >> 20;
                float a = g_ssrc[src * H + hh] + sd + g_etab[L][et * H + hh];
                a = (a > 0.f) ? a : NEG * a;
                s_aw[grp][jj][hh] = a;
                float mn = fmaxf(m, a);
                s = s * __expf(m - mn) + __expf(a - mn);
                m = mn;
            }
#pragma unroll
            for (int o = 4; o <= 16; o <<= 1) {
                float m2 = __shfl_xor_sync(0xffffffffu, m, o);
                float s2 = __shfl_xor_sync(0xffffffffu, s, o);
                float mn = fmaxf(m, m2);
                s = s * __expf(m - mn) + s2 * __expf(m2 - mn);
                m = mn;
            }
            float inv = 1.f / s;
            for (int jj = j0; jj < D; jj += 8)
                s_aw[grp][jj][hh] = __expf(s_aw[grp][jj][hh] - m) * inv;
        }
        __syncwarp();
        if (lane < K) {
            for (int jj = 0; jj < D; jj++) {
                int src = s_pk[grp][jj] & 0xFFFFF;
                float v = h[(size_t)src * K + lane];
                a0 += s_aw[grp][jj][0] * v;
                a1 += s_aw[grp][jj][1] * v;
                a2 += s_aw[grp][jj][2] * v;
                a3 += s_aw[grp][jj][3] * v;
            }
        }
    } else {
        // fallback (deg > CAP): serial softmax, inline-recompute weights
        int hh = lane & 3;
        int j0 = lane >> 2;
        float sd = g_sdst[n * H + hh];
        float m = -1e30f, s = 0.f;
        for (int jj = j0; jj < D; jj += 8) {
            int p = g_se[b0 + jj];
            int src = p & 0xFFFFF, et = p >> 20;
            float a = g_ssrc[src * H + hh] + sd + g_etab[L][et * H + hh];
            a = (a > 0.f) ? a : NEG * a;
            float mn = fmaxf(m, a);
            s = s * __expf(m - mn) + __expf(a - mn);
            m = mn;
        }
#pragma unroll
        for (int o = 4; o <= 16; o <<= 1) {
            float m2 = __shfl_xor_sync(0xffffffffu, m, o);
            float s2 = __shfl_xor_sync(0xffffffffu, s, o);
            float mn = fmaxf(m, m2);
            s = s * __expf(m - mn) + s2 * __expf(m2 - mn);
            m = mn;
        }
        float inv = 1.f / s;
        // broadcast per-head (m, inv) from lanes 0..3
        float m4[H], i4[H];
#pragma unroll
        for (int h4 = 0; h4 < H; h4++) {
            m4[h4] = __shfl_sync(0xffffffffu, m, h4);
            i4[h4] = __shfl_sync(0xffffffffu, inv, h4);
        }
        if (lane < K) {
            float sd4[H];
#pragma unroll
            for (int h4 = 0; h4 < H; h4++) sd4[h4] = g_sdst[n * H + h4];
            for (int jj = 0; jj < D; jj++) {
                int p = g_se[b0 + jj];
                int src = p & 0xFFFFF, et = p >> 20;
                float v = h[(size_t)src * K + lane];
#pragma unroll
                for (int h4 = 0; h4 < H; h4++) {
                    float a = g_ssrc[src * H + h4] + sd4[h4] + g_etab[L][et * H + h4];
                    a = (a > 0.f) ? a : NEG * a;
                    float w = __expf(a - m4[h4]) * i4[h4];
                    if (h4 == 0) a0 += w * v;
                    else if (h4 == 1) a1 += w * v;
                    else if (h4 == 2) a2 += w * v;
                    else a3 += w * v;
                }
            }
        }
    }

    if (lane < K) {
        size_t base = (size_t)n * (H * K) + lane;
        if (CVT) {
            __half* ah = reinterpret_cast<__half*>(aggf);
            ah[base]         = __float2half(a0);
            ah[base + K]     = __float2half(a1);
            ah[base + 2 * K] = __float2half(a2);
            ah[base + 3 * K] = __float2half(a3);
        } else {
            aggf[base]         = a0;
            aggf[base + K]     = a1;
            aggf[base + 2 * K] = a2;
            aggf[base + 3 * K] = a3;
        }
    }
}

// ------- L3 edge kernel: 2 nodes per 128-thr block, half2 gathers ----------
__global__ void k_gat_edge3(const __half2* __restrict__ h2, __half2* __restrict__ agg2) {
    constexpr int CAP = 128;
    __shared__ int   s_pk[2][CAP];
    __shared__ float s_aw[2][CAP][H];
    __shared__ float s_ms[2][2][H];

    int grp  = threadIdx.x >> 6;          // 0/1: node within block
    int gtid = threadIdx.x & 63;
    int lane = threadIdx.x & 31;
    int wing = (threadIdx.x >> 5) & 1;    // warp within group
    int n = blockIdx.x * 2 + grp;
    int b0 = g_rowptr[n], b1 = g_rowptr[n + 1];
    int D = b1 - b0;
    bool fast = (D <= CAP);

    // phase 0: load edge list
    if (fast)
        for (int j = gtid; j < D; j += 64) s_pk[grp][j] = g_se[b0 + j];
    __syncthreads();

    // phase 1: softmax (group's warp 0)
    if (wing == 0) {
        int hh = lane & 3;
        int j0 = lane >> 2;
        float sd = g_sdst[n * H + hh];
        float m = -1e30f, s = 0.f;
        if (fast) {
            for (int jj = j0; jj < D; jj += 8) {
                int p = s_pk[grp][jj];
                int src = p & 0xFFFFF, et = p >> 20;
                float a = g_ssrc[src * H + hh] + sd + g_etab[2][et * H + hh];
                a = (a > 0.f) ? a : NEG * a;
                s_aw[grp][jj][hh] = a;
                float mn = fmaxf(m, a);
                s = s * __expf(m - mn) + __expf(a - mn);
                m = mn;
            }
        } else {
            for (int jj = j0; jj < D; jj += 8) {
                int p = g_se[b0 + jj];
                int src = p & 0xFFFFF, et = p >> 20;
                float a = g_ssrc[src * H + hh] + sd + g_etab[2][et * H + hh];
                a = (a > 0.f) ? a : NEG * a;
                float mn = fmaxf(m, a);
                s = s * __expf(m - mn) + __expf(a - mn);
                m = mn;
            }
        }
#pragma unroll
        for (int o = 4; o <= 16; o <<= 1) {
            float m2 = __shfl_xor_sync(0xffffffffu, m, o);
            float s2 = __shfl_xor_sync(0xffffffffu, s, o);
            float mn = fmaxf(m, m2);
            s = s * __expf(m - mn) + s2 * __expf(m2 - mn);
            m = mn;
        }
        float inv = 1.f / s;
        if (fast) {
            for (int jj = j0; jj < D; jj += 8)
                s_aw[grp][jj][hh] = __expf(s_aw[grp][jj][hh] - m) * inv;
        } else if (lane < H) {
            s_ms[grp][0][lane] = m;
            s_ms[grp][1][lane] = inv;
        }
    }
    __syncthreads();

    // phase 2: aggregation (64 threads, half2 channel pairs)
    float ax[H], ay[H];
#pragma unroll
    for (int h4 = 0; h4 < H; h4++) { ax[h4] = 0.f; ay[h4] = 0.f; }

    if (fast) {
        for (int jj = 0; jj < D; jj++) {
            int src = s_pk[grp][jj] & 0xFFFFF;
            float2 v = __half22float2(h2[(size_t)src * 64 + gtid]);
#pragma unroll
            for (int h4 = 0; h4 < H; h4++) {
                float w = s_aw[grp][jj][h4];
                ax[h4] += w * v.x;
                ay[h4] += w * v.y;
            }
        }
    } else {
        float m4[H], i4[H], sd4[H];
#pragma unroll
        for (int h4 = 0; h4 < H; h4++) {
            m4[h4] = s_ms[grp][0][h4];
            i4[h4] = s_ms[grp][1][h4];
            sd4[h4] = g_sdst[n * H + h4];
        }
        for (int jj = 0; jj < D; jj++) {
            int p = g_se[b0 + jj];
            int src = p & 0xFFFFF, et = p >> 20;
            float2 v = __half22float2(h2[(size_t)src * 64 + gtid]);
#pragma unroll
            for (int h4 = 0; h4 < H; h4++) {
                float a = g_ssrc[src * H + h4] + sd4[h4] + g_etab[2][et * H + h4];
                a = (a > 0.f) ? a : NEG * a;
                float w = __expf(a - m4[h4]) * i4[h4];
                ax[h4] += w * v.x;
                ay[h4] += w * v.y;
            }
        }
    }

    size_t base = (size_t)n * 256 + gtid;   // half2 units: row = 4 heads * 64
#pragma unroll
    for (int h4 = 0; h4 < H; h4++)
        agg2[base + h4 * 64] = __floats2half2_rn(ax[h4], ay[h4]);
}

// ------------- small GEMM (layer 1): C = A[N,K] @ B[K,NN] + bias -----------
__global__ void k_gemm_small(const float* __restrict__ A, const float* __restrict__ B,
                             const float* __restrict__ bias, float* __restrict__ C,
                             int K, int NN, int relu) {
    int idx = blockIdx.x * blockDim.x + threadIdx.x;
    int n = idx / NN, d = idx % NN;
    if (n >= N) return;
    const float* ar = A + (size_t)n * K;
    float acc = 0.f;
    for (int k = 0; k < K; k++) acc += ar[k] * B[k * NN + d];
    acc += bias[d];
    if (relu) acc = fmaxf(acc, 0.f);
    C[(size_t)n * NN + d] = acc;
}

// ------- fp16 TC GEMM: 128x128x32 tiles, 3-stage cp.async ring -------------
constexpr int STG_BYTES = 128 * 40 * 2 * 2;    // A+B per stage = 20480 B
constexpr int SMEM_HF   = 3 * STG_BYTES;       // 61440 B

__device__ __forceinline__ uint32_t smem_u32(const void* p) {
    uint32_t a;
    asm("{ .reg .u64 t; cvta.to.shared.u64 t, %1; cvt.u32.u64 %0, t; }" : "=r"(a) : "l"(p));
    return a;
}

__global__ void __launch_bounds__(256, 2)
k_gemm_hf(const __half* __restrict__ A, const __half* __restrict__ Bt,
          const float* __restrict__ bias, float* __restrict__ C,
          __half2* __restrict__ Ch2, int K, int NN, int relu) {
    extern __shared__ char hsm[];
    int tid = threadIdx.x;
    int wid = tid >> 5, lane = tid & 31;
    int bm = blockIdx.y * 128, bn = blockIdx.x * 128;
    int wm = (wid >> 2) * 64;
    int wn = (wid & 3) * 32;
    int grp = lane >> 2, tig = lane & 3;

    auto stA = [&](int s) { return reinterpret_cast<__half*>(hsm + s * STG_BYTES); };
    auto stB = [&](int s) { return reinterpret_cast<__half*>(hsm + s * STG_BYTES) + 128 * 40; };

    float c[4][4][4];
#pragma unroll
    for (int mt = 0; mt < 4; mt++)
#pragma unroll
        for (int nt = 0; nt < 4; nt++)
#pragma unroll
            for (int q = 0; q < 4; q++) c[mt][nt][q] = 0.f;

    int nk = K >> 5;

    auto copy_tile = [&](int s, int k0) {
        __half* As = stA(s);
        __half* Bs = stB(s);
#pragma unroll
        for (int i = 0; i < 2; i++) {
            int f = tid + i * 256;
            int m = f >> 2, q = f & 3;
            uint32_t dst = smem_u32(&As[m * 40 + q * 8]);
            const __half* src = &A[(size_t)(bm + m) * K + k0 + q * 8];
            asm volatile("cp.async.ca.shared.global [%0], [%1], 16;" :: "r"(dst), "l"(src));
        }
#pragma unroll
        for (int i = 0; i < 2; i++) {
            int f = tid + i * 256;
            int nrow = f >> 2, q = f & 3;
            uint32_t dst = smem_u32(&Bs[nrow * 40 + q * 8]);
            const __half* src = &Bt[(size_t)(bn + nrow) * K + k0 + q * 8];
            asm volatile("cp.async.ca.shared.global [%0], [%1], 16;" :: "r"(dst), "l"(src));
        }
        asm volatile("cp.async.commit_group;");
    };

    copy_tile(0, 0);
    copy_tile(1, 32);

    int mtx = lane >> 3;
    int rin = lane & 7;

    for (int it = 0; it < nk; it++) {
        int cur = it % 3;
        if (it + 1 < nk) asm volatile("cp.async.wait_group 1;");
        else             asm volatile("cp.async.wait_group 0;");
        __syncthreads();
        if (it + 2 < nk) copy_tile((it + 2) % 3, (it + 2) * 32);

        __half* As = stA(cur);
        __half* Bs = stB(cur);
#pragma unroll
        for (int ks = 0; ks < 2; ks++) {
            uint32_t a[4][4], b[4][2];
#pragma unroll
            for (int mt = 0; mt < 4; mt++) {
                int row = wm + mt * 16 + (mtx & 1) * 8 + rin;
                int col = ks * 16 + (mtx >> 1) * 8;
                uint32_t addr = smem_u32(&As[row * 40 + col]);
                asm volatile("ldmatrix.sync.aligned.m8n8.x4.shared.b16 {%0,%1,%2,%3}, [%4];"
                             : "=r"(a[mt][0]), "=r"(a[mt][1]), "=r"(a[mt][2]), "=r"(a[mt][3])
                             : "r"(addr));
            }
#pragma unroll
            for (int np = 0; np < 2; np++) {
                int row = wn + np * 16 + (mtx >> 1) * 8 + rin;
                int col = ks * 16 + (mtx & 1) * 8;
                uint32_t addr = smem_u32(&Bs[row * 40 + col]);
                asm volatile("ldmatrix.sync.aligned.m8n8.x4.shared.b16 {%0,%1,%2,%3}, [%4];"
                             : "=r"(b[np * 2][0]), "=r"(b[np * 2][1]),
                               "=r"(b[np * 2 + 1][0]), "=r"(b[np * 2 + 1][1])
                             : "r"(addr));
            }
#pragma unroll
            for (int mt = 0; mt < 4; mt++)
#pragma unroll
                for (int nt = 0; nt < 4; nt++) {
                    asm volatile(
                        "mma.sync.aligned.m16n8k16.row.col.f32.f16.f16.f32 "
                        "{%0,%1,%2,%3}, {%4,%5,%6,%7}, {%8,%9}, {%0,%1,%2,%3};"
                        : "+f"(c[mt][nt][0]), "+f"(c[mt][nt][1]),
                          "+f"(c[mt][nt][2]), "+f"(c[mt][nt][3])
                        : "r"(a[mt][0]), "r"(a[mt][1]), "r"(a[mt][2]), "r"(a[mt][3]),
                          "r"(b[nt][0]), "r"(b[nt][1]));
                }
        }
        __syncthreads();
    }

#pragma unroll
    for (int mt = 0; mt < 4; mt++) {
#pragma unroll
        for (int nt = 0; nt < 4; nt++) {
            int col = bn + wn + nt * 8 + tig * 2;
            float bv0 = bias[col], bv1 = bias[col + 1];
            int r0 = bm + wm + mt * 16 + grp;
            float v00 = c[mt][nt][0] + bv0, v01 = c[mt][nt][1] + bv1;
            float v10 = c[mt][nt][2] + bv0, v11 = c[mt][nt][3] + bv1;
            if (relu) {
                v00 = fmaxf(v00, 0.f); v01 = fmaxf(v01, 0.f);
                v10 = fmaxf(v10, 0.f); v11 = fmaxf(v11, 0.f);
            }
            C[(size_t)r0 * NN + col]           = v00;
            C[(size_t)r0 * NN + col + 1]       = v01;
            C[(size_t)(r0 + 8) * NN + col]     = v10;
            C[(size_t)(r0 + 8) * NN + col + 1] = v11;
            if (Ch2) {
                Ch2[((size_t)r0 * NN + col) >> 1]       = __floats2half2_rn(v00, v01);
                Ch2[((size_t)(r0 + 8) * NN + col) >> 1] = __floats2half2_rn(v10, v11);
            }
        }
    }
}

// ---------------------------------------------------------------------------
extern "C" void kernel_launch(void* const* d_in, const int* in_sizes, int n_in,
                              void* d_out, int out_size) {
    const float* x   = (const float*)d_in[0];
    const int*   eit = (const int*)d_in[1];
    const float* W1  = (const float*)d_in[2];
    const float* We1 = (const float*)d_in[3];
    const float* as1 = (const float*)d_in[4];
    const float* ad1 = (const float*)d_in[5];
    const float* ae1 = (const float*)d_in[6];
    const float* b1  = (const float*)d_in[7];
    const float* W2  = (const float*)d_in[8];
    const float* We2 = (const float*)d_in[9];
    const float* as2 = (const float*)d_in[10];
    const float* ad2 = (const float*)d_in[11];
    const float* ae2 = (const float*)d_in[12];
    const float* b2  = (const float*)d_in[13];
    const float* W3  = (const float*)d_in[14];
    const float* We3 = (const float*)d_in[15];
    const float* as3 = (const float*)d_in[16];
    const float* ad3 = (const float*)d_in[17];
    const float* ae3 = (const float*)d_in[18];
    const float* b3  = (const float*)d_in[19];
    float* out = (float*)d_out;

    float *agg = nullptr, *hbuf = nullptr, *wst1 = nullptr;
    __half *wst2 = nullptr, *wst3 = nullptr;
    __half2 *hbufh2 = nullptr;
    cudaGetSymbolAddress((void**)&agg, g_agg);
    cudaGetSymbolAddress((void**)&hbuf, g_hbuf);
    cudaGetSymbolAddress((void**)&wst1, g_wst1);
    cudaGetSymbolAddress((void**)&wst2, g_wst2);
    cudaGetSymbolAddress((void**)&wst3, g_wst3);
    cudaGetSymbolAddress((void**)&hbufh2, g_hbufh2);
    const __half* aggh = (const __half*)agg;
    __half2* agg2 = (__half2*)agg;

    cudaFuncSetAttribute(k_gemm_hf, cudaFuncAttributeMaxDynamicSharedMemorySize, SMEM_HF);

    // ---- graph build + fused prep ----
    k_zero_deg<<<N / 256, 256>>>();
    k_build<<<E / 256, 256>>>(eit);
    k_scan<<<1, 1024>>>();
    k_scatter<<<E / 256, 256>>>();
    k_prep_all<<<1102, 256>>>(W1, as1, ad1, We1, ae1,
                              W2, as2, ad2, We2, ae2,
                              W3, as3, ad3, We3, ae3);

    // ---- layer 1: K=16 -> dout=32 (fp32 SIMT) ----
    k_scores<<<N / 8, 256>>>(x, 16, 0);
    k_gat_edge<16, false><<<N / 4, 128>>>(x, agg, 0);
    k_gemm_small<<<(N * 32) / 256, 256>>>(agg, wst1, b1, hbuf, 64, 32, 1);

    // ---- layer 2: K=32 -> dout=128 (fp16 TC GEMM; emits fp32 + half2) ----
    k_scores<<<N / 8, 256>>>(hbuf, 32, 1);
    k_gat_edge<32, true><<<N / 4, 128>>>(hbuf, agg, 1);
    k_gemm_hf<<<dim3(1, N / 128), 256, SMEM_HF>>>(aggh, wst2, b2, hbuf, hbufh2, 128, 128, 1);

    // ---- layer 3: K=128 -> dout=512 (half2 gathers; fp16 TC GEMM -> out) --
    k_scores<<<N / 8, 256>>>(hbuf, 128, 2);
    k_gat_edge3<<<N / 2, 128>>>(hbufh2, agg2);
    k_gemm_hf<<<dim3(4, N / 128), 256, SMEM_HF>>>(aggh, wst3, b3, out, nullptr, 512, 512, 0);
}